// round 1
// baseline (speedup 1.0000x reference)
#include <cuda_runtime.h>
#include <math.h>

// Problem constants
#define BB 2
#define TT 2048
#define CC 1024
#define HH 16
#define DD 64
#define M_TOK (BB*TT)     // 4096
#define N_QKV (3*CC)      // 3072

// Scratch (allocation-free rule: __device__ globals)
__device__ float g_qkv[M_TOK * N_QKV];   // 48 MB: qkv = x@W_attn + b
__device__ float g_y[M_TOK * CC];        // 16 MB: attention output [B,T,H,D] flattened

// ---------------------------------------------------------------------------
// Register-tiled fp32 GEMM:  C[M,N] = A[M,K] @ B[K,N] + bias[N]
// Block tile 64x64, K-step 16, 256 threads, 4x4 micro-tile per thread.
// Assumes M%64==0, N%64==0, K%16==0 (true for all our shapes).
// ---------------------------------------------------------------------------
__global__ __launch_bounds__(256)
void gemm_bias_kernel(const float* __restrict__ A, const float* __restrict__ Bm,
                      const float* __restrict__ bias, float* __restrict__ Cm,
                      int Mdim, int Ndim, int Kdim)
{
    __shared__ float As[16][68];   // transposed: As[k][m], pad for STS/LDS
    __shared__ float Bs[16][64];   // natural:    Bs[k][n]

    const int tid = threadIdx.x;
    const int tx = tid & 15;       // n-direction
    const int ty = tid >> 4;       // m-direction
    const int m0 = blockIdx.y * 64;
    const int n0 = blockIdx.x * 64;

    // load mapping
    const int arow = tid >> 2, aq = tid & 3;    // A: 64 rows x 4 quads
    const int brow = tid >> 4, bq = tid & 15;   // B: 16 rows x 16 quads

    const float* Aptr = A + (size_t)(m0 + arow) * Kdim + 4 * aq;
    const float* Bptr = Bm + (size_t)brow * Ndim + n0 + 4 * bq;

    float acc[4][4] = {};

    for (int k0 = 0; k0 < Kdim; k0 += 16) {
        float4 av = *(const float4*)(Aptr + k0);
        float4 bv = *(const float4*)(Bptr + (size_t)k0 * Ndim);
        __syncthreads();  // previous compute done before overwrite
        As[4*aq + 0][arow] = av.x;
        As[4*aq + 1][arow] = av.y;
        As[4*aq + 2][arow] = av.z;
        As[4*aq + 3][arow] = av.w;
        *(float4*)&Bs[brow][4*bq] = bv;
        __syncthreads();

        #pragma unroll
        for (int k = 0; k < 16; ++k) {
            float4 a = *(const float4*)&As[k][4*ty];
            float4 b = *(const float4*)&Bs[k][4*tx];
            acc[0][0] += a.x*b.x; acc[0][1] += a.x*b.y; acc[0][2] += a.x*b.z; acc[0][3] += a.x*b.w;
            acc[1][0] += a.y*b.x; acc[1][1] += a.y*b.y; acc[1][2] += a.y*b.z; acc[1][3] += a.y*b.w;
            acc[2][0] += a.z*b.x; acc[2][1] += a.z*b.y; acc[2][2] += a.z*b.z; acc[2][3] += a.z*b.w;
            acc[3][0] += a.w*b.x; acc[3][1] += a.w*b.y; acc[3][2] += a.w*b.z; acc[3][3] += a.w*b.w;
        }
    }

    float4 bb = *(const float4*)(bias + n0 + 4*tx);
    #pragma unroll
    for (int i = 0; i < 4; ++i) {
        float4 out;
        out.x = acc[i][0] + bb.x;
        out.y = acc[i][1] + bb.y;
        out.z = acc[i][2] + bb.z;
        out.w = acc[i][3] + bb.w;
        *(float4*)(Cm + (size_t)(m0 + 4*ty + i) * Ndim + n0 + 4*tx) = out;
    }
}

// ---------------------------------------------------------------------------
// Flash attention, fp32, causal. One CTA per (b*h, q-tile of 64).
// Q/K/V read directly from g_qkv (token stride 3072, col offsets 0/C/2C).
// Output Y in [B,T,H*D] layout so projection GEMM reads it contiguously.
// Online softmax, 4x4 per-thread register tiles, scale = 1/32.
// ---------------------------------------------------------------------------
#define NEG_BIG (-1e30f)

__global__ __launch_bounds__(256)
void attn_kernel(const float* __restrict__ qkv, float* __restrict__ Y)
{
    extern __shared__ float sm[];
    float (*Qs)[65] = reinterpret_cast<float(*)[65]>(sm);
    float (*Ks)[65] = reinterpret_cast<float(*)[65]>(sm + 64*65);
    float (*Vs)[65] = reinterpret_cast<float(*)[65]>(sm + 2*64*65);
    float (*Ss)[65] = reinterpret_cast<float(*)[65]>(sm + 3*64*65);

    const int bh = blockIdx.y;              // 0..B*H-1
    const int b  = bh >> 4;
    const int h  = bh & 15;
    const int qt = blockIdx.x;              // q-tile index 0..31
    const int q0 = qt * 64;

    const int tid = threadIdx.x;
    const int tx  = tid & 15;               // key / d-col direction
    const int ty  = tid >> 4;               // query row direction

    const size_t tok_base = (size_t)(b * TT) * N_QKV;

    // ---- load Q tile (64 x 64) into Qs ----
    #pragma unroll
    for (int rep = 0; rep < 4; ++rep) {
        int idx = tid + rep * 256;          // 0..1023
        int r = idx >> 4, qd = idx & 15;
        float4 v = *(const float4*)(qkv + tok_base + (size_t)(q0 + r) * N_QKV + h*DD + 4*qd);
        Qs[r][4*qd + 0] = v.x; Qs[r][4*qd + 1] = v.y;
        Qs[r][4*qd + 2] = v.z; Qs[r][4*qd + 3] = v.w;
    }

    float m[4], l[4], o[4][4];
    #pragma unroll
    for (int i = 0; i < 4; ++i) {
        m[i] = NEG_BIG; l[i] = 0.f;
        #pragma unroll
        for (int j = 0; j < 4; ++j) o[i][j] = 0.f;
    }

    const float scale = 0.03125f;           // 1/sqrt(1024)

    for (int kt = 0; kt <= qt; ++kt) {
        const int k0 = kt * 64;

        // global loads for K and V tiles into registers
        float4 kv[4], vv[4];
        #pragma unroll
        for (int rep = 0; rep < 4; ++rep) {
            int idx = tid + rep * 256;
            int r = idx >> 4, qd = idx & 15;
            size_t rowb = tok_base + (size_t)(k0 + r) * N_QKV + h*DD + 4*qd;
            kv[rep] = *(const float4*)(qkv + rowb + CC);
            vv[rep] = *(const float4*)(qkv + rowb + 2*CC);
        }
        __syncthreads();   // prior O-gemm reads finished
        #pragma unroll
        for (int rep = 0; rep < 4; ++rep) {
            int idx = tid + rep * 256;
            int r = idx >> 4, qd = idx & 15;
            Ks[r][4*qd+0] = kv[rep].x; Ks[r][4*qd+1] = kv[rep].y;
            Ks[r][4*qd+2] = kv[rep].z; Ks[r][4*qd+3] = kv[rep].w;
            Vs[r][4*qd+0] = vv[rep].x; Vs[r][4*qd+1] = vv[rep].y;
            Vs[r][4*qd+2] = vv[rep].z; Vs[r][4*qd+3] = vv[rep].w;
        }
        __syncthreads();

        // ---- S = scale * Q K^T (4x4 per thread) ----
        float s[4][4] = {};
        #pragma unroll
        for (int d = 0; d < 64; ++d) {
            float a0 = Qs[4*ty+0][d], a1 = Qs[4*ty+1][d];
            float a2 = Qs[4*ty+2][d], a3 = Qs[4*ty+3][d];
            float b0 = Ks[4*tx+0][d], b1 = Ks[4*tx+1][d];
            float b2 = Ks[4*tx+2][d], b3 = Ks[4*tx+3][d];
            s[0][0] += a0*b0; s[0][1] += a0*b1; s[0][2] += a0*b2; s[0][3] += a0*b3;
            s[1][0] += a1*b0; s[1][1] += a1*b1; s[1][2] += a1*b2; s[1][3] += a1*b3;
            s[2][0] += a2*b0; s[2][1] += a2*b1; s[2][2] += a2*b2; s[2][3] += a2*b3;
            s[3][0] += a3*b0; s[3][1] += a3*b1; s[3][2] += a3*b2; s[3][3] += a3*b3;
        }
        #pragma unroll
        for (int i = 0; i < 4; ++i)
            #pragma unroll
            for (int j = 0; j < 4; ++j)
                s[i][j] *= scale;

        // causal mask (only diagonal tile needs it)
        if (kt == qt) {
            #pragma unroll
            for (int i = 0; i < 4; ++i) {
                int qi = q0 + 4*ty + i;
                #pragma unroll
                for (int j = 0; j < 4; ++j)
                    if (k0 + 4*tx + j > qi) s[i][j] = NEG_BIG;
            }
        }

        // ---- online softmax ----
        #pragma unroll
        for (int i = 0; i < 4; ++i) {
            float rm = fmaxf(fmaxf(s[i][0], s[i][1]), fmaxf(s[i][2], s[i][3]));
            #pragma unroll
            for (int off = 8; off >= 1; off >>= 1)
                rm = fmaxf(rm, __shfl_xor_sync(0xffffffffu, rm, off));
            float mn = fmaxf(m[i], rm);
            float alpha = __expf(m[i] - mn);
            float ps = 0.f;
            #pragma unroll
            for (int j = 0; j < 4; ++j) {
                float p = __expf(s[i][j] - mn);
                s[i][j] = p;
                ps += p;
            }
            #pragma unroll
            for (int off = 8; off >= 1; off >>= 1)
                ps += __shfl_xor_sync(0xffffffffu, ps, off);
            l[i] = l[i] * alpha + ps;
            m[i] = mn;
            #pragma unroll
            for (int j = 0; j < 4; ++j) o[i][j] *= alpha;
        }

        // write P to shared
        #pragma unroll
        for (int i = 0; i < 4; ++i)
            #pragma unroll
            for (int j = 0; j < 4; ++j)
                Ss[4*ty+i][4*tx+j] = s[i][j];
        __syncthreads();

        // ---- O += P @ V ----
        #pragma unroll
        for (int k = 0; k < 64; ++k) {
            float a0 = Ss[4*ty+0][k], a1 = Ss[4*ty+1][k];
            float a2 = Ss[4*ty+2][k], a3 = Ss[4*ty+3][k];
            float b0 = Vs[k][4*tx+0], b1 = Vs[k][4*tx+1];
            float b2 = Vs[k][4*tx+2], b3 = Vs[k][4*tx+3];
            o[0][0] += a0*b0; o[0][1] += a0*b1; o[0][2] += a0*b2; o[0][3] += a0*b3;
            o[1][0] += a1*b0; o[1][1] += a1*b1; o[1][2] += a1*b2; o[1][3] += a1*b3;
            o[2][0] += a2*b0; o[2][1] += a2*b1; o[2][2] += a2*b2; o[2][3] += a2*b3;
            o[3][0] += a3*b0; o[3][1] += a3*b1; o[3][2] += a3*b2; o[3][3] += a3*b3;
        }
    }

    // ---- normalize and store: Y[b, q, h*64 + d] ----
    #pragma unroll
    for (int i = 0; i < 4; ++i) {
        float inv = 1.0f / l[i];
        float4 out;
        out.x = o[i][0] * inv; out.y = o[i][1] * inv;
        out.z = o[i][2] * inv; out.w = o[i][3] * inv;
        *(float4*)(Y + (size_t)(b*TT + q0 + 4*ty + i) * CC + h*DD + 4*tx) = out;
    }
}

// ---------------------------------------------------------------------------
// Launch
// ---------------------------------------------------------------------------
extern "C" void kernel_launch(void* const* d_in, const int* in_sizes, int n_in,
                              void* d_out, int out_size)
{
    const float* x      = (const float*)d_in[0];
    const float* W_attn = (const float*)d_in[1];
    const float* b_attn = (const float*)d_in[2];
    const float* W_proj = (const float*)d_in[3];
    const float* b_proj = (const float*)d_in[4];
    float* out = (float*)d_out;

    float* qkv_ptr = nullptr;
    float* y_ptr   = nullptr;
    cudaGetSymbolAddress((void**)&qkv_ptr, g_qkv);
    cudaGetSymbolAddress((void**)&y_ptr, g_y);

    const int attn_smem = 4 * 64 * 65 * sizeof(float);   // 66560 B
    cudaFuncSetAttribute(attn_kernel, cudaFuncAttributeMaxDynamicSharedMemorySize, attn_smem);

    // 1) qkv = x @ W_attn + b_attn   [4096,1024]x[1024,3072]
    gemm_bias_kernel<<<dim3(N_QKV/64, M_TOK/64), 256>>>(x, W_attn, b_attn, qkv_ptr,
                                                        M_TOK, N_QKV, CC);

    // 2) flash attention -> y [4096,1024]
    attn_kernel<<<dim3(TT/64, BB*HH), 256, attn_smem>>>(qkv_ptr, y_ptr);

    // 3) out = y @ W_proj + b_proj   [4096,1024]x[1024,1024]
    gemm_bias_kernel<<<dim3(CC/64, M_TOK/64), 256>>>(y_ptr, W_proj, b_proj, out,
                                                     M_TOK, CC, CC);
}

// round 3
// speedup vs baseline: 1.5526x; 1.5526x over previous
#include <cuda_runtime.h>
#include <math.h>

// Problem constants
#define BB 2
#define TT 2048
#define CC 1024
#define HH 16
#define DD 64
#define M_TOK (BB*TT)     // 4096
#define N_QKV (3*CC)      // 3072

// Scratch (allocation-free rule: __device__ globals)
__device__ float g_qkv[M_TOK * N_QKV];   // 48 MB
__device__ float g_y[M_TOK * CC];        // 16 MB

// ---------------------------------------------------------------------------
// TF32 tensor-core GEMM: C[M,N] = A[M,K] @ B[K,N] + bias[N]
// BM=128, BN=128, BK=16, 512 threads (16 warps in 4x4 grid, 32x32 per warp).
// mma.sync.aligned.m16n8k8 tf32. Requires M%128==0, N%128==0, K%16==0.
// ---------------------------------------------------------------------------
#define BM 128
#define BN 128
#define BKG 16
#define SKEW 8   // row pitch BM+8 = 136: fragment loads are bank-conflict-free

// cvt.rna.tf32.f32 needs a .b32 destination register
__device__ __forceinline__ unsigned to_tf32u(float x) {
    unsigned r;
    asm("cvt.rna.tf32.f32 %0, %1;" : "=r"(r) : "f"(x));
    return r;
}
__device__ __forceinline__ float to_tf32f(float x) {
    return __uint_as_float(to_tf32u(x));
}

__device__ __forceinline__ void mma_tf32(float c[4], const unsigned a[4], const unsigned b[2]) {
    asm volatile(
        "mma.sync.aligned.m16n8k8.row.col.f32.tf32.tf32.f32 "
        "{%0,%1,%2,%3}, {%4,%5,%6,%7}, {%8,%9}, {%0,%1,%2,%3};\n"
        : "+f"(c[0]), "+f"(c[1]), "+f"(c[2]), "+f"(c[3])
        : "r"(a[0]), "r"(a[1]), "r"(a[2]), "r"(a[3]), "r"(b[0]), "r"(b[1]));
}

__global__ __launch_bounds__(512)
void gemm_tf32_kernel(const float* __restrict__ A, const float* __restrict__ Bm,
                      const float* __restrict__ bias, float* __restrict__ Cm,
                      int Mdim, int Ndim, int Kdim)
{
    __shared__ float As[BKG][BM + SKEW];   // [k][m]
    __shared__ float Bs[BKG][BN + SKEW];   // [k][n]

    const int tid  = threadIdx.x;
    const int lane = tid & 31;
    const int wid  = tid >> 5;
    const int g    = lane >> 2;            // group id (0..7)
    const int t    = lane & 3;             // thread-in-group (0..3)
    const int warp_m = wid & 3;            // 4 warps along M
    const int warp_n = wid >> 2;           // 4 warps along N
    const int m0 = blockIdx.y * BM;
    const int n0 = blockIdx.x * BN;

    // global load mapping
    const int arow = tid >> 2, aq = tid & 3;     // A: 128 rows x 4 float4
    const int brow = tid >> 5, bq = tid & 31;    // B: 16 rows x 32 float4

    const float* Aptr = A + (size_t)(m0 + arow) * Kdim + 4 * aq;
    const float* Bptr = Bm + (size_t)brow * Ndim + n0 + 4 * bq;

    float c[2][4][4];
    #pragma unroll
    for (int mi = 0; mi < 2; ++mi)
        #pragma unroll
        for (int ni = 0; ni < 4; ++ni)
            #pragma unroll
            for (int j = 0; j < 4; ++j) c[mi][ni][j] = 0.f;

    // prefetch first tile
    float4 av = *(const float4*)Aptr;
    float4 bv = *(const float4*)Bptr;

    for (int k0 = 0; k0 < Kdim; k0 += BKG) {
        __syncthreads();    // previous compute done before smem overwrite
        As[4*aq + 0][arow] = to_tf32f(av.x);
        As[4*aq + 1][arow] = to_tf32f(av.y);
        As[4*aq + 2][arow] = to_tf32f(av.z);
        As[4*aq + 3][arow] = to_tf32f(av.w);
        float4 bc;
        bc.x = to_tf32f(bv.x); bc.y = to_tf32f(bv.y);
        bc.z = to_tf32f(bv.z); bc.w = to_tf32f(bv.w);
        *(float4*)&Bs[brow][4*bq] = bc;
        __syncthreads();

        // prefetch next tile (overlaps with mma below)
        if (k0 + BKG < Kdim) {
            av = *(const float4*)(Aptr + k0 + BKG);
            bv = *(const float4*)(Bptr + (size_t)(k0 + BKG) * Ndim);
        }

        #pragma unroll
        for (int kk = 0; kk < 2; ++kk) {
            unsigned afr[2][4], bfr[4][2];
            #pragma unroll
            for (int mi = 0; mi < 2; ++mi) {
                int mb = warp_m * 32 + mi * 16;
                afr[mi][0] = __float_as_uint(As[kk*8 + t    ][mb + g    ]);
                afr[mi][1] = __float_as_uint(As[kk*8 + t    ][mb + g + 8]);
                afr[mi][2] = __float_as_uint(As[kk*8 + t + 4][mb + g    ]);
                afr[mi][3] = __float_as_uint(As[kk*8 + t + 4][mb + g + 8]);
            }
            #pragma unroll
            for (int ni = 0; ni < 4; ++ni) {
                int nb = warp_n * 32 + ni * 8;
                bfr[ni][0] = __float_as_uint(Bs[kk*8 + t    ][nb + g]);
                bfr[ni][1] = __float_as_uint(Bs[kk*8 + t + 4][nb + g]);
            }
            #pragma unroll
            for (int mi = 0; mi < 2; ++mi)
                #pragma unroll
                for (int ni = 0; ni < 4; ++ni)
                    mma_tf32(c[mi][ni], afr[mi], bfr[ni]);
        }
    }

    // epilogue: C layout c0,c1 -> (row g, cols 2t,2t+1); c2,c3 -> row g+8
    #pragma unroll
    for (int mi = 0; mi < 2; ++mi) {
        #pragma unroll
        for (int ni = 0; ni < 4; ++ni) {
            int row = m0 + warp_m * 32 + mi * 16 + g;
            int col = n0 + warp_n * 32 + ni * 8 + 2 * t;
            float2 bb = *(const float2*)(bias + col);
            float2 o0, o1;
            o0.x = c[mi][ni][0] + bb.x; o0.y = c[mi][ni][1] + bb.y;
            o1.x = c[mi][ni][2] + bb.x; o1.y = c[mi][ni][3] + bb.y;
            *(float2*)(Cm + (size_t)row * Ndim + col) = o0;
            *(float2*)(Cm + (size_t)(row + 8) * Ndim + col) = o1;
        }
    }
}

// ---------------------------------------------------------------------------
// Flash attention, fp32, causal (unchanged from R1).
// ---------------------------------------------------------------------------
#define NEG_BIG (-1e30f)

__global__ __launch_bounds__(256)
void attn_kernel(const float* __restrict__ qkv, float* __restrict__ Y)
{
    extern __shared__ float sm[];
    float (*Qs)[65] = reinterpret_cast<float(*)[65]>(sm);
    float (*Ks)[65] = reinterpret_cast<float(*)[65]>(sm + 64*65);
    float (*Vs)[65] = reinterpret_cast<float(*)[65]>(sm + 2*64*65);
    float (*Ss)[65] = reinterpret_cast<float(*)[65]>(sm + 3*64*65);

    const int bh = blockIdx.y;
    const int b  = bh >> 4;
    const int h  = bh & 15;
    const int qt = blockIdx.x;
    const int q0 = qt * 64;

    const int tid = threadIdx.x;
    const int tx  = tid & 15;
    const int ty  = tid >> 4;

    const size_t tok_base = (size_t)(b * TT) * N_QKV;

    #pragma unroll
    for (int rep = 0; rep < 4; ++rep) {
        int idx = tid + rep * 256;
        int r = idx >> 4, qd = idx & 15;
        float4 v = *(const float4*)(qkv + tok_base + (size_t)(q0 + r) * N_QKV + h*DD + 4*qd);
        Qs[r][4*qd + 0] = v.x; Qs[r][4*qd + 1] = v.y;
        Qs[r][4*qd + 2] = v.z; Qs[r][4*qd + 3] = v.w;
    }

    float m[4], l[4], o[4][4];
    #pragma unroll
    for (int i = 0; i < 4; ++i) {
        m[i] = NEG_BIG; l[i] = 0.f;
        #pragma unroll
        for (int j = 0; j < 4; ++j) o[i][j] = 0.f;
    }

    const float scale = 0.03125f;

    for (int kt = 0; kt <= qt; ++kt) {
        const int k0 = kt * 64;

        float4 kv[4], vv[4];
        #pragma unroll
        for (int rep = 0; rep < 4; ++rep) {
            int idx = tid + rep * 256;
            int r = idx >> 4, qd = idx & 15;
            size_t rowb = tok_base + (size_t)(k0 + r) * N_QKV + h*DD + 4*qd;
            kv[rep] = *(const float4*)(qkv + rowb + CC);
            vv[rep] = *(const float4*)(qkv + rowb + 2*CC);
        }
        __syncthreads();
        #pragma unroll
        for (int rep = 0; rep < 4; ++rep) {
            int idx = tid + rep * 256;
            int r = idx >> 4, qd = idx & 15;
            Ks[r][4*qd+0] = kv[rep].x; Ks[r][4*qd+1] = kv[rep].y;
            Ks[r][4*qd+2] = kv[rep].z; Ks[r][4*qd+3] = kv[rep].w;
            Vs[r][4*qd+0] = vv[rep].x; Vs[r][4*qd+1] = vv[rep].y;
            Vs[r][4*qd+2] = vv[rep].z; Vs[r][4*qd+3] = vv[rep].w;
        }
        __syncthreads();

        float s[4][4] = {};
        #pragma unroll
        for (int d = 0; d < 64; ++d) {
            float a0 = Qs[4*ty+0][d], a1 = Qs[4*ty+1][d];
            float a2 = Qs[4*ty+2][d], a3 = Qs[4*ty+3][d];
            float b0 = Ks[4*tx+0][d], b1 = Ks[4*tx+1][d];
            float b2 = Ks[4*tx+2][d], b3 = Ks[4*tx+3][d];
            s[0][0] += a0*b0; s[0][1] += a0*b1; s[0][2] += a0*b2; s[0][3] += a0*b3;
            s[1][0] += a1*b0; s[1][1] += a1*b1; s[1][2] += a1*b2; s[1][3] += a1*b3;
            s[2][0] += a2*b0; s[2][1] += a2*b1; s[2][2] += a2*b2; s[2][3] += a2*b3;
            s[3][0] += a3*b0; s[3][1] += a3*b1; s[3][2] += a3*b2; s[3][3] += a3*b3;
        }
        #pragma unroll
        for (int i = 0; i < 4; ++i)
            #pragma unroll
            for (int j = 0; j < 4; ++j)
                s[i][j] *= scale;

        if (kt == qt) {
            #pragma unroll
            for (int i = 0; i < 4; ++i) {
                int qi = q0 + 4*ty + i;
                #pragma unroll
                for (int j = 0; j < 4; ++j)
                    if (k0 + 4*tx + j > qi) s[i][j] = NEG_BIG;
            }
        }

        #pragma unroll
        for (int i = 0; i < 4; ++i) {
            float rm = fmaxf(fmaxf(s[i][0], s[i][1]), fmaxf(s[i][2], s[i][3]));
            #pragma unroll
            for (int off = 8; off >= 1; off >>= 1)
                rm = fmaxf(rm, __shfl_xor_sync(0xffffffffu, rm, off));
            float mn = fmaxf(m[i], rm);
            float alpha = __expf(m[i] - mn);
            float ps = 0.f;
            #pragma unroll
            for (int j = 0; j < 4; ++j) {
                float p = __expf(s[i][j] - mn);
                s[i][j] = p;
                ps += p;
            }
            #pragma unroll
            for (int off = 8; off >= 1; off >>= 1)
                ps += __shfl_xor_sync(0xffffffffu, ps, off);
            l[i] = l[i] * alpha + ps;
            m[i] = mn;
            #pragma unroll
            for (int j = 0; j < 4; ++j) o[i][j] *= alpha;
        }

        #pragma unroll
        for (int i = 0; i < 4; ++i)
            #pragma unroll
            for (int j = 0; j < 4; ++j)
                Ss[4*ty+i][4*tx+j] = s[i][j];
        __syncthreads();

        #pragma unroll
        for (int k = 0; k < 64; ++k) {
            float a0 = Ss[4*ty+0][k], a1 = Ss[4*ty+1][k];
            float a2 = Ss[4*ty+2][k], a3 = Ss[4*ty+3][k];
            float b0 = Vs[k][4*tx+0], b1 = Vs[k][4*tx+1];
            float b2 = Vs[k][4*tx+2], b3 = Vs[k][4*tx+3];
            o[0][0] += a0*b0; o[0][1] += a0*b1; o[0][2] += a0*b2; o[0][3] += a0*b3;
            o[1][0] += a1*b0; o[1][1] += a1*b1; o[1][2] += a1*b2; o[1][3] += a1*b3;
            o[2][0] += a2*b0; o[2][1] += a2*b1; o[2][2] += a2*b2; o[2][3] += a2*b3;
            o[3][0] += a3*b0; o[3][1] += a3*b1; o[3][2] += a3*b2; o[3][3] += a3*b3;
        }
    }

    #pragma unroll
    for (int i = 0; i < 4; ++i) {
        float inv = 1.0f / l[i];
        float4 out;
        out.x = o[i][0] * inv; out.y = o[i][1] * inv;
        out.z = o[i][2] * inv; out.w = o[i][3] * inv;
        *(float4*)(Y + (size_t)(b*TT + q0 + 4*ty + i) * CC + h*DD + 4*tx) = out;
    }
}

// ---------------------------------------------------------------------------
// Launch
// ---------------------------------------------------------------------------
extern "C" void kernel_launch(void* const* d_in, const int* in_sizes, int n_in,
                              void* d_out, int out_size)
{
    const float* x      = (const float*)d_in[0];
    const float* W_attn = (const float*)d_in[1];
    const float* b_attn = (const float*)d_in[2];
    const float* W_proj = (const float*)d_in[3];
    const float* b_proj = (const float*)d_in[4];
    float* out = (float*)d_out;

    float* qkv_ptr = nullptr;
    float* y_ptr   = nullptr;
    cudaGetSymbolAddress((void**)&qkv_ptr, g_qkv);
    cudaGetSymbolAddress((void**)&y_ptr, g_y);

    const int attn_smem = 4 * 64 * 65 * sizeof(float);
    cudaFuncSetAttribute(attn_kernel, cudaFuncAttributeMaxDynamicSharedMemorySize, attn_smem);

    // 1) qkv = x @ W_attn + b_attn
    gemm_tf32_kernel<<<dim3(N_QKV/BN, M_TOK/BM), 512>>>(x, W_attn, b_attn, qkv_ptr,
                                                        M_TOK, N_QKV, CC);

    // 2) flash attention
    attn_kernel<<<dim3(TT/64, BB*HH), 256, attn_smem>>>(qkv_ptr, y_ptr);

    // 3) out = y @ W_proj + b_proj
    gemm_tf32_kernel<<<dim3(CC/BN, M_TOK/BM), 512>>>(y_ptr, W_proj, b_proj, out,
                                                     M_TOK, CC, CC);
}

// round 4
// speedup vs baseline: 2.6431x; 1.7024x over previous
#include <cuda_runtime.h>
#include <math.h>

// Problem constants
#define BB 2
#define TT 2048
#define CC 1024
#define HH 16
#define DD 64
#define M_TOK (BB*TT)     // 4096
#define N_QKV (3*CC)      // 3072

// Scratch (allocation-free rule: __device__ globals)
__device__ float g_qkv[M_TOK * N_QKV];   // 48 MB
__device__ float g_y[M_TOK * CC];        // 16 MB

// cvt.rna.tf32.f32 needs a .b32 destination register
__device__ __forceinline__ unsigned to_tf32u(float x) {
    unsigned r;
    asm("cvt.rna.tf32.f32 %0, %1;" : "=r"(r) : "f"(x));
    return r;
}
__device__ __forceinline__ float to_tf32f(float x) {
    return __uint_as_float(to_tf32u(x));
}

__device__ __forceinline__ void mma_tf32(float c[4], const unsigned a[4], const unsigned b[2]) {
    asm volatile(
        "mma.sync.aligned.m16n8k8.row.col.f32.tf32.tf32.f32 "
        "{%0,%1,%2,%3}, {%4,%5,%6,%7}, {%8,%9}, {%0,%1,%2,%3};\n"
        : "+f"(c[0]), "+f"(c[1]), "+f"(c[2]), "+f"(c[3])
        : "r"(a[0]), "r"(a[1]), "r"(a[2]), "r"(a[3]), "r"(b[0]), "r"(b[1]));
}

// ---------------------------------------------------------------------------
// TF32 tensor-core GEMM (unchanged from R3): C = A @ B + bias
// ---------------------------------------------------------------------------
#define BM 128
#define BN 128
#define BKG 16
#define SKEW 8

__global__ __launch_bounds__(512)
void gemm_tf32_kernel(const float* __restrict__ A, const float* __restrict__ Bm,
                      const float* __restrict__ bias, float* __restrict__ Cm,
                      int Mdim, int Ndim, int Kdim)
{
    __shared__ float As[BKG][BM + SKEW];   // [k][m]
    __shared__ float Bs[BKG][BN + SKEW];   // [k][n]

    const int tid  = threadIdx.x;
    const int lane = tid & 31;
    const int wid  = tid >> 5;
    const int g    = lane >> 2;
    const int t    = lane & 3;
    const int warp_m = wid & 3;
    const int warp_n = wid >> 2;
    const int m0 = blockIdx.y * BM;
    const int n0 = blockIdx.x * BN;

    const int arow = tid >> 2, aq = tid & 3;
    const int brow = tid >> 5, bq = tid & 31;

    const float* Aptr = A + (size_t)(m0 + arow) * Kdim + 4 * aq;
    const float* Bptr = Bm + (size_t)brow * Ndim + n0 + 4 * bq;

    float c[2][4][4];
    #pragma unroll
    for (int mi = 0; mi < 2; ++mi)
        #pragma unroll
        for (int ni = 0; ni < 4; ++ni)
            #pragma unroll
            for (int j = 0; j < 4; ++j) c[mi][ni][j] = 0.f;

    float4 av = *(const float4*)Aptr;
    float4 bv = *(const float4*)Bptr;

    for (int k0 = 0; k0 < Kdim; k0 += BKG) {
        __syncthreads();
        As[4*aq + 0][arow] = to_tf32f(av.x);
        As[4*aq + 1][arow] = to_tf32f(av.y);
        As[4*aq + 2][arow] = to_tf32f(av.z);
        As[4*aq + 3][arow] = to_tf32f(av.w);
        float4 bc;
        bc.x = to_tf32f(bv.x); bc.y = to_tf32f(bv.y);
        bc.z = to_tf32f(bv.z); bc.w = to_tf32f(bv.w);
        *(float4*)&Bs[brow][4*bq] = bc;
        __syncthreads();

        if (k0 + BKG < Kdim) {
            av = *(const float4*)(Aptr + k0 + BKG);
            bv = *(const float4*)(Bptr + (size_t)(k0 + BKG) * Ndim);
        }

        #pragma unroll
        for (int kk = 0; kk < 2; ++kk) {
            unsigned afr[2][4], bfr[4][2];
            #pragma unroll
            for (int mi = 0; mi < 2; ++mi) {
                int mb = warp_m * 32 + mi * 16;
                afr[mi][0] = __float_as_uint(As[kk*8 + t    ][mb + g    ]);
                afr[mi][1] = __float_as_uint(As[kk*8 + t    ][mb + g + 8]);
                afr[mi][2] = __float_as_uint(As[kk*8 + t + 4][mb + g    ]);
                afr[mi][3] = __float_as_uint(As[kk*8 + t + 4][mb + g + 8]);
            }
            #pragma unroll
            for (int ni = 0; ni < 4; ++ni) {
                int nb = warp_n * 32 + ni * 8;
                bfr[ni][0] = __float_as_uint(Bs[kk*8 + t    ][nb + g]);
                bfr[ni][1] = __float_as_uint(Bs[kk*8 + t + 4][nb + g]);
            }
            #pragma unroll
            for (int mi = 0; mi < 2; ++mi)
                #pragma unroll
                for (int ni = 0; ni < 4; ++ni)
                    mma_tf32(c[mi][ni], afr[mi], bfr[ni]);
        }
    }

    #pragma unroll
    for (int mi = 0; mi < 2; ++mi) {
        #pragma unroll
        for (int ni = 0; ni < 4; ++ni) {
            int row = m0 + warp_m * 32 + mi * 16 + g;
            int col = n0 + warp_n * 32 + ni * 8 + 2 * t;
            float2 bb = *(const float2*)(bias + col);
            float2 o0, o1;
            o0.x = c[mi][ni][0] + bb.x; o0.y = c[mi][ni][1] + bb.y;
            o1.x = c[mi][ni][2] + bb.x; o1.y = c[mi][ni][3] + bb.y;
            *(float2*)(Cm + (size_t)row * Ndim + col) = o0;
            *(float2*)(Cm + (size_t)(row + 8) * Ndim + col) = o1;
        }
    }
}

// ---------------------------------------------------------------------------
// TF32 tensor-core flash attention, causal.
// QTILE=128 q-rows per CTA, KTILE=64 keys per iteration, 256 threads (8 warps).
// Warp w owns q-rows [w*16, w*16+16): full-width S row -> warp-local softmax.
// m16n8k8 TF32 mma for S=Q K^T and O += P V. P staged through smem.
// ---------------------------------------------------------------------------
#define QTILE 128
#define KTILE 64
#define AP 68            // pitch for Qs/Ks/Ps: bank = 4g+t, conflict-free frags
#define VP 72            // pitch for Vs: bank = 8t+g, conflict-free frags
#define NEG_BIG (-1e30f)

__global__ __launch_bounds__(256)
void attn_tc_kernel(const float* __restrict__ qkv, float* __restrict__ Y)
{
    extern __shared__ float smf[];
    float* Qs = smf;                       // [128][AP]
    float* Ks = Qs + QTILE * AP;           // [64][AP]
    float* Vs = Ks + KTILE * AP;           // [64][VP]
    float* Ps = Vs + KTILE * VP;           // [128][AP]

    const int bh = blockIdx.y;
    const int b  = bh >> 4;
    const int h  = bh & 15;
    const int q0 = blockIdx.x * QTILE;

    const int tid  = threadIdx.x;
    const int lane = tid & 31;
    const int wid  = tid >> 5;
    const int g    = lane >> 2;
    const int t    = lane & 3;
    const int wr   = wid * 16;             // warp's first row within tile

    const size_t tok_base = (size_t)b * TT * N_QKV;
    const float scale = 0.03125f;          // 1/sqrt(1024)

    // ---- load Q tile (128 x 64), rounded to tf32 ----
    #pragma unroll
    for (int it = 0; it < 8; ++it) {
        int idx = tid + it * 256;          // 0..2047 float4s
        int r = idx >> 4, q = idx & 15;
        float4 v = *(const float4*)(qkv + tok_base + (size_t)(q0 + r) * N_QKV + h*DD + 4*q);
        float* dst = Qs + r * AP + 4*q;
        dst[0] = to_tf32f(v.x); dst[1] = to_tf32f(v.y);
        dst[2] = to_tf32f(v.z); dst[3] = to_tf32f(v.w);
    }

    float o[8][4];
    #pragma unroll
    for (int n = 0; n < 8; ++n)
        #pragma unroll
        for (int j = 0; j < 4; ++j) o[n][j] = 0.f;
    float mrow[2] = {NEG_BIG, NEG_BIG};
    float lrow[2] = {0.f, 0.f};

    const int q_hi  = q0 + wr + 15;                  // warp's last q row
    const int ktmax = (q0 + QTILE - 1) / KTILE;      // tiles the CTA must load

    for (int kt = 0; kt <= ktmax; ++kt) {
        const int k0 = kt * KTILE;

        // prefetch K,V tile into registers (issues before the barrier)
        float4 kv[4], vv[4];
        #pragma unroll
        for (int it = 0; it < 4; ++it) {
            int idx = tid + it * 256;      // 0..1023 float4s
            int r = idx >> 4, q = idx & 15;
            size_t rowb = tok_base + (size_t)(k0 + r) * N_QKV + h*DD + 4*q;
            kv[it] = *(const float4*)(qkv + rowb + CC);
            vv[it] = *(const float4*)(qkv + rowb + 2*CC);
        }
        __syncthreads();   // everyone done reading previous Ks/Vs
        #pragma unroll
        for (int it = 0; it < 4; ++it) {
            int idx = tid + it * 256;
            int r = idx >> 4, q = idx & 15;
            float* kd = Ks + r * AP + 4*q;
            kd[0] = to_tf32f(kv[it].x); kd[1] = to_tf32f(kv[it].y);
            kd[2] = to_tf32f(kv[it].z); kd[3] = to_tf32f(kv[it].w);
            float* vd = Vs + r * VP + 4*q;
            vd[0] = to_tf32f(vv[it].x); vd[1] = to_tf32f(vv[it].y);
            vd[2] = to_tf32f(vv[it].z); vd[3] = to_tf32f(vv[it].w);
        }
        __syncthreads();

        if (k0 <= q_hi) {
            // ---- S = Q K^T ----
            float s[8][4];
            #pragma unroll
            for (int n = 0; n < 8; ++n)
                #pragma unroll
                for (int j = 0; j < 4; ++j) s[n][j] = 0.f;

            #pragma unroll
            for (int kk = 0; kk < 8; ++kk) {
                unsigned qa[4];
                const float* qb = Qs + (wr + g) * AP + kk*8 + t;
                qa[0] = __float_as_uint(qb[0]);
                qa[1] = __float_as_uint(qb[8 * AP]);
                qa[2] = __float_as_uint(qb[4]);
                qa[3] = __float_as_uint(qb[8 * AP + 4]);
                #pragma unroll
                for (int n = 0; n < 8; ++n) {
                    unsigned bf[2];
                    const float* kb = Ks + (n*8 + g) * AP + kk*8 + t;
                    bf[0] = __float_as_uint(kb[0]);
                    bf[1] = __float_as_uint(kb[4]);
                    mma_tf32(s[n], qa, bf);
                }
            }

            #pragma unroll
            for (int n = 0; n < 8; ++n)
                #pragma unroll
                for (int j = 0; j < 4; ++j) s[n][j] *= scale;

            // causal mask (only near the diagonal for this warp)
            if (k0 + KTILE - 1 > q0 + wr) {
                int r0 = q0 + wr + g, r1 = r0 + 8;
                #pragma unroll
                for (int n = 0; n < 8; ++n) {
                    int key = k0 + n*8 + 2*t;
                    if (key     > r0) s[n][0] = NEG_BIG;
                    if (key + 1 > r0) s[n][1] = NEG_BIG;
                    if (key     > r1) s[n][2] = NEG_BIG;
                    if (key + 1 > r1) s[n][3] = NEG_BIG;
                }
            }

            // ---- online softmax (two rows per thread: g and g+8) ----
            #pragma unroll
            for (int half = 0; half < 2; ++half) {
                float rm = NEG_BIG;
                #pragma unroll
                for (int n = 0; n < 8; ++n)
                    rm = fmaxf(rm, fmaxf(s[n][2*half], s[n][2*half+1]));
                rm = fmaxf(rm, __shfl_xor_sync(0xffffffffu, rm, 1));
                rm = fmaxf(rm, __shfl_xor_sync(0xffffffffu, rm, 2));
                float mn = fmaxf(mrow[half], rm);
                float alpha = __expf(mrow[half] - mn);
                float ps = 0.f;
                #pragma unroll
                for (int n = 0; n < 8; ++n) {
                    float p0 = __expf(s[n][2*half]   - mn);
                    float p1 = __expf(s[n][2*half+1] - mn);
                    s[n][2*half] = p0; s[n][2*half+1] = p1;
                    ps += p0 + p1;
                }
                ps += __shfl_xor_sync(0xffffffffu, ps, 1);
                ps += __shfl_xor_sync(0xffffffffu, ps, 2);
                lrow[half] = lrow[half] * alpha + ps;
                mrow[half] = mn;
                #pragma unroll
                for (int n = 0; n < 8; ++n) {
                    o[n][2*half]   *= alpha;
                    o[n][2*half+1] *= alpha;
                }
            }

            // ---- stage P in smem (tf32) for A-fragment reload ----
            #pragma unroll
            for (int n = 0; n < 8; ++n) {
                float* p0 = Ps + (wr + g) * AP + n*8 + 2*t;
                p0[0] = to_tf32f(s[n][0]); p0[1] = to_tf32f(s[n][1]);
                float* p1 = Ps + (wr + g + 8) * AP + n*8 + 2*t;
                p1[0] = to_tf32f(s[n][2]); p1[1] = to_tf32f(s[n][3]);
            }
            __syncwarp();

            // ---- O += P V ----
            #pragma unroll
            for (int kk = 0; kk < 8; ++kk) {
                unsigned pa[4];
                const float* pb = Ps + (wr + g) * AP + kk*8 + t;
                pa[0] = __float_as_uint(pb[0]);
                pa[1] = __float_as_uint(pb[8 * AP]);
                pa[2] = __float_as_uint(pb[4]);
                pa[3] = __float_as_uint(pb[8 * AP + 4]);
                #pragma unroll
                for (int n = 0; n < 8; ++n) {
                    unsigned bf[2];
                    const float* vb = Vs + (kk*8 + t) * VP + n*8 + g;
                    bf[0] = __float_as_uint(vb[0]);
                    bf[1] = __float_as_uint(vb[4 * VP]);
                    mma_tf32(o[n], pa, bf);
                }
            }
        }
    }

    // ---- normalize + store: Y[b, row, h*64 + col] ----
    #pragma unroll
    for (int half = 0; half < 2; ++half) {
        float inv = 1.0f / lrow[half];
        int row = q0 + wr + g + half * 8;
        float* yb = Y + (size_t)(b * TT + row) * CC + h*DD + 2*t;
        #pragma unroll
        for (int n = 0; n < 8; ++n) {
            float2 ov;
            ov.x = o[n][2*half]   * inv;
            ov.y = o[n][2*half+1] * inv;
            *(float2*)(yb + n*8) = ov;
        }
    }
}

// ---------------------------------------------------------------------------
// Launch
// ---------------------------------------------------------------------------
extern "C" void kernel_launch(void* const* d_in, const int* in_sizes, int n_in,
                              void* d_out, int out_size)
{
    const float* x      = (const float*)d_in[0];
    const float* W_attn = (const float*)d_in[1];
    const float* b_attn = (const float*)d_in[2];
    const float* W_proj = (const float*)d_in[3];
    const float* b_proj = (const float*)d_in[4];
    float* out = (float*)d_out;

    float* qkv_ptr = nullptr;
    float* y_ptr   = nullptr;
    cudaGetSymbolAddress((void**)&qkv_ptr, g_qkv);
    cudaGetSymbolAddress((void**)&y_ptr, g_y);

    const int attn_smem = (QTILE*AP + KTILE*AP + KTILE*VP + QTILE*AP) * sizeof(float);
    cudaFuncSetAttribute(attn_tc_kernel, cudaFuncAttributeMaxDynamicSharedMemorySize, attn_smem);

    // 1) qkv = x @ W_attn + b_attn
    gemm_tf32_kernel<<<dim3(N_QKV/BN, M_TOK/BM), 512>>>(x, W_attn, b_attn, qkv_ptr,
                                                        M_TOK, N_QKV, CC);

    // 2) flash attention (tensor cores)
    attn_tc_kernel<<<dim3(TT/QTILE, BB*HH), 256, attn_smem>>>(qkv_ptr, y_ptr);

    // 3) out = y @ W_proj + b_proj
    gemm_tf32_kernel<<<dim3(CC/BN, M_TOK/BM), 512>>>(y_ptr, W_proj, b_proj, out,
                                                     M_TOK, CC, CC);
}

// round 5
// speedup vs baseline: 3.0157x; 1.1410x over previous
#include <cuda_runtime.h>
#include <math.h>

// Problem constants
#define BB 2
#define TT 2048
#define CC 1024
#define HH 16
#define DD 64
#define M_TOK (BB*TT)     // 4096
#define N_QKV (3*CC)      // 3072

// Scratch (allocation-free rule: __device__ globals)
__device__ float g_qkv[M_TOK * N_QKV];   // 48 MB
__device__ float g_y[M_TOK * CC];        // 16 MB
__device__ float g_xr[M_TOK * CC];       // 16 MB : tf32-rounded x
__device__ float g_wa[CC * N_QKV];       // 12 MB : tf32-rounded W_attn
__device__ float g_wp[CC * CC];          //  4 MB : tf32-rounded W_proj

// cvt.rna.tf32.f32 needs a .b32 destination register
__device__ __forceinline__ unsigned to_tf32u(float x) {
    unsigned r;
    asm("cvt.rna.tf32.f32 %0, %1;" : "=r"(r) : "f"(x));
    return r;
}
__device__ __forceinline__ float to_tf32f(float x) {
    return __uint_as_float(to_tf32u(x));
}

__device__ __forceinline__ void mma_tf32(float c[4], const unsigned a[4], const unsigned b[2]) {
    asm volatile(
        "mma.sync.aligned.m16n8k8.row.col.f32.tf32.tf32.f32 "
        "{%0,%1,%2,%3}, {%4,%5,%6,%7}, {%8,%9}, {%0,%1,%2,%3};\n"
        : "+f"(c[0]), "+f"(c[1]), "+f"(c[2]), "+f"(c[3])
        : "r"(a[0]), "r"(a[1]), "r"(a[2]), "r"(a[3]), "r"(b[0]), "r"(b[1]));
}

__device__ __forceinline__ void cp_async16(void* smem, const void* gmem) {
    unsigned saddr = (unsigned)__cvta_generic_to_shared(smem);
    asm volatile("cp.async.cg.shared.global [%0], [%1], 16;\n" :: "r"(saddr), "l"(gmem));
}
#define CP_COMMIT() asm volatile("cp.async.commit_group;\n" ::: "memory")
#define CP_WAIT1()  asm volatile("cp.async.wait_group 1;\n" ::: "memory")

// ---------------------------------------------------------------------------
// tf32 rounding pre-pass (elementwise, float4)
// ---------------------------------------------------------------------------
__global__ void round_tf32_kernel(const float* __restrict__ in, float* __restrict__ out, int n4)
{
    int i = blockIdx.x * blockDim.x + threadIdx.x;
    if (i < n4) {
        float4 v = ((const float4*)in)[i];
        float4 r;
        r.x = to_tf32f(v.x); r.y = to_tf32f(v.y);
        r.z = to_tf32f(v.z); r.w = to_tf32f(v.w);
        ((float4*)out)[i] = r;
    }
}

// ---------------------------------------------------------------------------
// TF32 tensor-core GEMM with 3-stage cp.async pipeline.
// C[M,N] = A[M,K] @ B[K,N] + bias[N].  A,B must be pre-rounded to tf32.
// BM=128, BN=128, BK=16, 512 threads (16 warps 4x4, 32x32 per warp).
// Smem: As [stage][m:128][k:16 pad to 20], Bs [stage][k:16][n:128 pad to 136].
// ---------------------------------------------------------------------------
#define BM 128
#define BN 128
#define BKG 16
#define NSTAGE 3
#define APITCH 20
#define BPITCH 136
#define GEMM_SMEM ((NSTAGE*BM*APITCH + NSTAGE*BKG*BPITCH) * 4)   // 30720+26112 = 56832 B

__global__ __launch_bounds__(512)
void gemm_tf32_pipe(const float* __restrict__ A, const float* __restrict__ Bm,
                    const float* __restrict__ bias, float* __restrict__ Cm,
                    int Mdim, int Ndim, int Kdim)
{
    extern __shared__ float gsm[];
    float* As = gsm;                            // [NSTAGE][BM][APITCH]
    float* Bs = gsm + NSTAGE * BM * APITCH;     // [NSTAGE][BKG][BPITCH]

    const int tid  = threadIdx.x;
    const int lane = tid & 31;
    const int wid  = tid >> 5;
    const int g    = lane >> 2;
    const int t    = lane & 3;
    const int warp_m = wid & 3;
    const int warp_n = wid >> 2;
    const int m0 = blockIdx.y * BM;
    const int n0 = blockIdx.x * BN;

    // cp.async mapping: one 16B op per thread per operand per stage
    const int arow = tid >> 2, akq = tid & 3;    // A: 128 rows x 4 float4 (k-dir)
    const int brow = tid >> 5, bnq = tid & 31;   // B: 16 rows x 32 float4 (n-dir)

    const float* Aptr = A + (size_t)(m0 + arow) * Kdim + 4 * akq;
    const float* Bptr = Bm + (size_t)brow * Ndim + n0 + 4 * bnq;

    float* Asw = As + arow * APITCH + 4 * akq;   // this thread's A slot (per stage offset added)
    float* Bsw = Bs + brow * BPITCH + 4 * bnq;

    const int ASTRIDE = BM * APITCH;
    const int BSTRIDE = BKG * BPITCH;

    float c[2][4][4];
    #pragma unroll
    for (int mi = 0; mi < 2; ++mi)
        #pragma unroll
        for (int ni = 0; ni < 4; ++ni)
            #pragma unroll
            for (int j = 0; j < 4; ++j) c[mi][ni][j] = 0.f;

    const int ntiles = Kdim / BKG;

    // prologue: fill stages 0 and 1
    cp_async16(Asw + 0 * ASTRIDE, Aptr + 0 * BKG);
    cp_async16(Bsw + 0 * BSTRIDE, Bptr + (size_t)(0 * BKG) * Ndim);
    CP_COMMIT();
    cp_async16(Asw + 1 * ASTRIDE, Aptr + 1 * BKG);
    cp_async16(Bsw + 1 * BSTRIDE, Bptr + (size_t)(1 * BKG) * Ndim);
    CP_COMMIT();

    int stage = 0;
    for (int i = 0; i < ntiles; ++i) {
        CP_WAIT1();          // tile i resident
        __syncthreads();

        const float* Ast = As + stage * ASTRIDE;
        const float* Bst = Bs + stage * BSTRIDE;

        #pragma unroll
        for (int kk = 0; kk < 2; ++kk) {
            unsigned afr[2][4], bfr[4][2];
            #pragma unroll
            for (int mi = 0; mi < 2; ++mi) {
                int mb = warp_m * 32 + mi * 16;
                const float* ab = Ast + (mb + g) * APITCH + kk*8 + t;
                afr[mi][0] = __float_as_uint(ab[0]);
                afr[mi][1] = __float_as_uint(ab[8 * APITCH]);
                afr[mi][2] = __float_as_uint(ab[4]);
                afr[mi][3] = __float_as_uint(ab[8 * APITCH + 4]);
            }
            #pragma unroll
            for (int ni = 0; ni < 4; ++ni) {
                int nb = warp_n * 32 + ni * 8;
                const float* bb = Bst + (kk*8 + t) * BPITCH + nb + g;
                bfr[ni][0] = __float_as_uint(bb[0]);
                bfr[ni][1] = __float_as_uint(bb[4 * BPITCH]);
            }
            #pragma unroll
            for (int mi = 0; mi < 2; ++mi)
                #pragma unroll
                for (int ni = 0; ni < 4; ++ni)
                    mma_tf32(c[mi][ni], afr[mi], bfr[ni]);
        }

        __syncthreads();     // stage consumed CTA-wide before refill below

        int nx = i + 2;
        if (nx < ntiles) {
            int ns = nx % NSTAGE;
            cp_async16(Asw + ns * ASTRIDE, Aptr + nx * BKG);
            cp_async16(Bsw + ns * BSTRIDE, Bptr + (size_t)(nx * BKG) * Ndim);
        }
        CP_COMMIT();         // commit (possibly empty) to keep group accounting
        stage = (stage + 1 == NSTAGE) ? 0 : stage + 1;
    }

    // epilogue
    #pragma unroll
    for (int mi = 0; mi < 2; ++mi) {
        #pragma unroll
        for (int ni = 0; ni < 4; ++ni) {
            int row = m0 + warp_m * 32 + mi * 16 + g;
            int col = n0 + warp_n * 32 + ni * 8 + 2 * t;
            float2 bb = *(const float2*)(bias + col);
            float2 o0, o1;
            o0.x = c[mi][ni][0] + bb.x; o0.y = c[mi][ni][1] + bb.y;
            o1.x = c[mi][ni][2] + bb.x; o1.y = c[mi][ni][3] + bb.y;
            *(float2*)(Cm + (size_t)row * Ndim + col) = o0;
            *(float2*)(Cm + (size_t)(row + 8) * Ndim + col) = o1;
        }
    }
}

// ---------------------------------------------------------------------------
// TF32 tensor-core flash attention, causal (as R4; y written tf32-rounded).
// ---------------------------------------------------------------------------
#define QTILE 128
#define KTILE 64
#define AP 68
#define VP 72
#define NEG_BIG (-1e30f)

__global__ __launch_bounds__(256)
void attn_tc_kernel(const float* __restrict__ qkv, float* __restrict__ Y)
{
    extern __shared__ float smf[];
    float* Qs = smf;
    float* Ks = Qs + QTILE * AP;
    float* Vs = Ks + KTILE * AP;
    float* Ps = Vs + KTILE * VP;

    const int bh = blockIdx.y;
    const int b  = bh >> 4;
    const int h  = bh & 15;
    const int q0 = blockIdx.x * QTILE;

    const int tid  = threadIdx.x;
    const int lane = tid & 31;
    const int wid  = tid >> 5;
    const int g    = lane >> 2;
    const int t    = lane & 3;
    const int wr   = wid * 16;

    const size_t tok_base = (size_t)b * TT * N_QKV;
    const float scale = 0.03125f;

    #pragma unroll
    for (int it = 0; it < 8; ++it) {
        int idx = tid + it * 256;
        int r = idx >> 4, q = idx & 15;
        float4 v = *(const float4*)(qkv + tok_base + (size_t)(q0 + r) * N_QKV + h*DD + 4*q);
        float* dst = Qs + r * AP + 4*q;
        dst[0] = to_tf32f(v.x); dst[1] = to_tf32f(v.y);
        dst[2] = to_tf32f(v.z); dst[3] = to_tf32f(v.w);
    }

    float o[8][4];
    #pragma unroll
    for (int n = 0; n < 8; ++n)
        #pragma unroll
        for (int j = 0; j < 4; ++j) o[n][j] = 0.f;
    float mrow[2] = {NEG_BIG, NEG_BIG};
    float lrow[2] = {0.f, 0.f};

    const int q_hi  = q0 + wr + 15;
    const int ktmax = (q0 + QTILE - 1) / KTILE;

    for (int kt = 0; kt <= ktmax; ++kt) {
        const int k0 = kt * KTILE;

        float4 kv[4], vv[4];
        #pragma unroll
        for (int it = 0; it < 4; ++it) {
            int idx = tid + it * 256;
            int r = idx >> 4, q = idx & 15;
            size_t rowb = tok_base + (size_t)(k0 + r) * N_QKV + h*DD + 4*q;
            kv[it] = *(const float4*)(qkv + rowb + CC);
            vv[it] = *(const float4*)(qkv + rowb + 2*CC);
        }
        __syncthreads();
        #pragma unroll
        for (int it = 0; it < 4; ++it) {
            int idx = tid + it * 256;
            int r = idx >> 4, q = idx & 15;
            float* kd = Ks + r * AP + 4*q;
            kd[0] = to_tf32f(kv[it].x); kd[1] = to_tf32f(kv[it].y);
            kd[2] = to_tf32f(kv[it].z); kd[3] = to_tf32f(kv[it].w);
            float* vd = Vs + r * VP + 4*q;
            vd[0] = to_tf32f(vv[it].x); vd[1] = to_tf32f(vv[it].y);
            vd[2] = to_tf32f(vv[it].z); vd[3] = to_tf32f(vv[it].w);
        }
        __syncthreads();

        if (k0 <= q_hi) {
            float s[8][4];
            #pragma unroll
            for (int n = 0; n < 8; ++n)
                #pragma unroll
                for (int j = 0; j < 4; ++j) s[n][j] = 0.f;

            #pragma unroll
            for (int kk = 0; kk < 8; ++kk) {
                unsigned qa[4];
                const float* qb = Qs + (wr + g) * AP + kk*8 + t;
                qa[0] = __float_as_uint(qb[0]);
                qa[1] = __float_as_uint(qb[8 * AP]);
                qa[2] = __float_as_uint(qb[4]);
                qa[3] = __float_as_uint(qb[8 * AP + 4]);
                #pragma unroll
                for (int n = 0; n < 8; ++n) {
                    unsigned bf[2];
                    const float* kb = Ks + (n*8 + g) * AP + kk*8 + t;
                    bf[0] = __float_as_uint(kb[0]);
                    bf[1] = __float_as_uint(kb[4]);
                    mma_tf32(s[n], qa, bf);
                }
            }

            #pragma unroll
            for (int n = 0; n < 8; ++n)
                #pragma unroll
                for (int j = 0; j < 4; ++j) s[n][j] *= scale;

            if (k0 + KTILE - 1 > q0 + wr) {
                int r0 = q0 + wr + g, r1 = r0 + 8;
                #pragma unroll
                for (int n = 0; n < 8; ++n) {
                    int key = k0 + n*8 + 2*t;
                    if (key     > r0) s[n][0] = NEG_BIG;
                    if (key + 1 > r0) s[n][1] = NEG_BIG;
                    if (key     > r1) s[n][2] = NEG_BIG;
                    if (key + 1 > r1) s[n][3] = NEG_BIG;
                }
            }

            #pragma unroll
            for (int half = 0; half < 2; ++half) {
                float rm = NEG_BIG;
                #pragma unroll
                for (int n = 0; n < 8; ++n)
                    rm = fmaxf(rm, fmaxf(s[n][2*half], s[n][2*half+1]));
                rm = fmaxf(rm, __shfl_xor_sync(0xffffffffu, rm, 1));
                rm = fmaxf(rm, __shfl_xor_sync(0xffffffffu, rm, 2));
                float mn = fmaxf(mrow[half], rm);
                float alpha = __expf(mrow[half] - mn);
                float ps = 0.f;
                #pragma unroll
                for (int n = 0; n < 8; ++n) {
                    float p0 = __expf(s[n][2*half]   - mn);
                    float p1 = __expf(s[n][2*half+1] - mn);
                    s[n][2*half] = p0; s[n][2*half+1] = p1;
                    ps += p0 + p1;
                }
                ps += __shfl_xor_sync(0xffffffffu, ps, 1);
                ps += __shfl_xor_sync(0xffffffffu, ps, 2);
                lrow[half] = lrow[half] * alpha + ps;
                mrow[half] = mn;
                #pragma unroll
                for (int n = 0; n < 8; ++n) {
                    o[n][2*half]   *= alpha;
                    o[n][2*half+1] *= alpha;
                }
            }

            #pragma unroll
            for (int n = 0; n < 8; ++n) {
                float* p0 = Ps + (wr + g) * AP + n*8 + 2*t;
                p0[0] = to_tf32f(s[n][0]); p0[1] = to_tf32f(s[n][1]);
                float* p1 = Ps + (wr + g + 8) * AP + n*8 + 2*t;
                p1[0] = to_tf32f(s[n][2]); p1[1] = to_tf32f(s[n][3]);
            }
            __syncwarp();

            #pragma unroll
            for (int kk = 0; kk < 8; ++kk) {
                unsigned pa[4];
                const float* pb = Ps + (wr + g) * AP + kk*8 + t;
                pa[0] = __float_as_uint(pb[0]);
                pa[1] = __float_as_uint(pb[8 * AP]);
                pa[2] = __float_as_uint(pb[4]);
                pa[3] = __float_as_uint(pb[8 * AP + 4]);
                #pragma unroll
                for (int n = 0; n < 8; ++n) {
                    unsigned bf[2];
                    const float* vb = Vs + (kk*8 + t) * VP + n*8 + g;
                    bf[0] = __float_as_uint(vb[0]);
                    bf[1] = __float_as_uint(vb[4 * VP]);
                    mma_tf32(o[n], pa, bf);
                }
            }
        }
    }

    // normalize + store tf32-rounded y (proj GEMM consumes it raw via cp.async)
    #pragma unroll
    for (int half = 0; half < 2; ++half) {
        float inv = 1.0f / lrow[half];
        int row = q0 + wr + g + half * 8;
        float* yb = Y + (size_t)(b * TT + row) * CC + h*DD + 2*t;
        #pragma unroll
        for (int n = 0; n < 8; ++n) {
            float2 ov;
            ov.x = to_tf32f(o[n][2*half]   * inv);
            ov.y = to_tf32f(o[n][2*half+1] * inv);
            *(float2*)(yb + n*8) = ov;
        }
    }
}

// ---------------------------------------------------------------------------
// Launch
// ---------------------------------------------------------------------------
extern "C" void kernel_launch(void* const* d_in, const int* in_sizes, int n_in,
                              void* d_out, int out_size)
{
    const float* x      = (const float*)d_in[0];
    const float* W_attn = (const float*)d_in[1];
    const float* b_attn = (const float*)d_in[2];
    const float* W_proj = (const float*)d_in[3];
    const float* b_proj = (const float*)d_in[4];
    float* out = (float*)d_out;

    float *qkv_ptr, *y_ptr, *xr_ptr, *wa_ptr, *wp_ptr;
    cudaGetSymbolAddress((void**)&qkv_ptr, g_qkv);
    cudaGetSymbolAddress((void**)&y_ptr, g_y);
    cudaGetSymbolAddress((void**)&xr_ptr, g_xr);
    cudaGetSymbolAddress((void**)&wa_ptr, g_wa);
    cudaGetSymbolAddress((void**)&wp_ptr, g_wp);

    const int attn_smem = (QTILE*AP + KTILE*AP + KTILE*VP + QTILE*AP) * sizeof(float);
    cudaFuncSetAttribute(attn_tc_kernel, cudaFuncAttributeMaxDynamicSharedMemorySize, attn_smem);
    cudaFuncSetAttribute(gemm_tf32_pipe, cudaFuncAttributeMaxDynamicSharedMemorySize, GEMM_SMEM);

    // 0) tf32 rounding pre-pass
    {
        int n4 = M_TOK * CC / 4;
        round_tf32_kernel<<<(n4 + 255)/256, 256>>>(x, xr_ptr, n4);
        n4 = CC * N_QKV / 4;
        round_tf32_kernel<<<(n4 + 255)/256, 256>>>(W_attn, wa_ptr, n4);
        n4 = CC * CC / 4;
        round_tf32_kernel<<<(n4 + 255)/256, 256>>>(W_proj, wp_ptr, n4);
    }

    // 1) qkv = xr @ War + b_attn
    gemm_tf32_pipe<<<dim3(N_QKV/BN, M_TOK/BM), 512, GEMM_SMEM>>>(
        xr_ptr, wa_ptr, b_attn, qkv_ptr, M_TOK, N_QKV, CC);

    // 2) flash attention (tensor cores), y written tf32-rounded
    attn_tc_kernel<<<dim3(TT/QTILE, BB*HH), 256, attn_smem>>>(qkv_ptr, y_ptr);

    // 3) out = y @ Wpr + b_proj
    gemm_tf32_pipe<<<dim3(CC/BN, M_TOK/BM), 512, GEMM_SMEM>>>(
        y_ptr, wp_ptr, b_proj, out, M_TOK, CC, CC);
}

// round 7
// speedup vs baseline: 3.0506x; 1.0116x over previous
#include <cuda_runtime.h>
#include <math.h>

// Problem constants
#define BB 2
#define TT 2048
#define CC 1024
#define HH 16
#define DD 64
#define M_TOK (BB*TT)     // 4096
#define N_QKV (3*CC)      // 3072

// Scratch (allocation-free rule: __device__ globals)
__device__ float g_qkv[M_TOK * N_QKV];   // 48 MB
__device__ float g_y[M_TOK * CC];        // 16 MB
__device__ float g_xr[M_TOK * CC];       // 16 MB : tf32-rounded x
__device__ float g_wa[CC * N_QKV];       // 12 MB : tf32-rounded W_attn
__device__ float g_wp[CC * CC];          //  4 MB : tf32-rounded W_proj

__device__ __forceinline__ unsigned to_tf32u(float x) {
    unsigned r;
    asm("cvt.rna.tf32.f32 %0, %1;" : "=r"(r) : "f"(x));
    return r;
}
__device__ __forceinline__ float to_tf32f(float x) {
    return __uint_as_float(to_tf32u(x));
}

__device__ __forceinline__ void mma_tf32(float c[4], const unsigned a[4], const unsigned b[2]) {
    asm volatile(
        "mma.sync.aligned.m16n8k8.row.col.f32.tf32.tf32.f32 "
        "{%0,%1,%2,%3}, {%4,%5,%6,%7}, {%8,%9}, {%0,%1,%2,%3};\n"
        : "+f"(c[0]), "+f"(c[1]), "+f"(c[2]), "+f"(c[3])
        : "r"(a[0]), "r"(a[1]), "r"(a[2]), "r"(a[3]), "r"(b[0]), "r"(b[1]));
}

__device__ __forceinline__ void cp_async16(void* smem, const void* gmem) {
    unsigned saddr = (unsigned)__cvta_generic_to_shared(smem);
    asm volatile("cp.async.cg.shared.global [%0], [%1], 16;\n" :: "r"(saddr), "l"(gmem));
}
#define CP_COMMIT() asm volatile("cp.async.commit_group;\n" ::: "memory")
#define CP_WAIT1()  asm volatile("cp.async.wait_group 1;\n" ::: "memory")

// ---------------------------------------------------------------------------
// tf32 rounding pre-pass
// ---------------------------------------------------------------------------
__global__ void round_tf32_kernel(const float* __restrict__ in, float* __restrict__ out, int n4)
{
    int i = blockIdx.x * blockDim.x + threadIdx.x;
    if (i < n4) {
        float4 v = ((const float4*)in)[i];
        float4 r;
        r.x = to_tf32f(v.x); r.y = to_tf32f(v.y);
        r.z = to_tf32f(v.z); r.w = to_tf32f(v.w);
        ((float4*)out)[i] = r;
    }
}

// ---------------------------------------------------------------------------
// TF32 GEMM, 3-stage cp.async pipeline, 64x64 warp tiles.
// C[M,N] = A[M,K] @ B[K,N] + bias[N].  A,B pre-rounded tf32.
// BM=128, BN=256, BK=16, 256 threads (8 warps, 2x4 grid, 64x64 per warp).
// Requires M%128==0, N%256==0, K%16==0.
// ---------------------------------------------------------------------------
#define BM 128
#define BN 256
#define BKG 16
#define NSTAGE 3
#define APITCH 20
#define BPITCH 264
#define ASTRIDE (BM * APITCH)       // 2560 floats / stage
#define BSTRIDE (BKG * BPITCH)      // 4224 floats / stage
#define GEMM_SMEM ((NSTAGE*ASTRIDE + NSTAGE*BSTRIDE) * 4)   // 81408 B

__global__ __launch_bounds__(256)
void gemm_tf32_pipe(const float* __restrict__ A, const float* __restrict__ Bm,
                    const float* __restrict__ bias, float* __restrict__ Cm,
                    int Mdim, int Ndim, int Kdim)
{
    extern __shared__ float gsm[];
    float* As = gsm;                            // [NSTAGE][BM][APITCH]
    float* Bs = gsm + NSTAGE * ASTRIDE;         // [NSTAGE][BKG][BPITCH]

    const int tid  = threadIdx.x;
    const int lane = tid & 31;
    const int wid  = tid >> 5;
    const int g    = lane >> 2;
    const int t    = lane & 3;
    const int warp_m = wid & 1;                 // 2 warps along M (64 each)
    const int warp_n = wid >> 1;                // 4 warps along N (64 each)
    const int m0 = blockIdx.y * BM;
    const int n0 = blockIdx.x * BN;

    // cp.async mapping
    // A: 128 rows x 4 float4 = 512 ops -> 2/thread (rows arow, arow+64)
    const int arow = tid >> 2, akq = tid & 3;
    // B: 16 rows x 64 float4 = 1024 ops -> 4/thread (rows brow+4j)
    const int brow = tid >> 6, bnq = tid & 63;

    const float* Aptr = A + (size_t)(m0 + arow) * Kdim + 4 * akq;
    const float* Bptr = Bm + (size_t)brow * Ndim + n0 + 4 * bnq;

    float* Asw = As + arow * APITCH + 4 * akq;
    float* Bsw = Bs + brow * BPITCH + 4 * bnq;

    float c[4][8][4];
    #pragma unroll
    for (int mi = 0; mi < 4; ++mi)
        #pragma unroll
        for (int ni = 0; ni < 8; ++ni)
            #pragma unroll
            for (int j = 0; j < 4; ++j) c[mi][ni][j] = 0.f;

    const int ntiles = Kdim / BKG;

    // prologue: fill stages 0,1
    #pragma unroll
    for (int st = 0; st < 2; ++st) {
        cp_async16(Asw + st*ASTRIDE,              Aptr + st*BKG);
        cp_async16(Asw + st*ASTRIDE + 64*APITCH,  Aptr + (size_t)64*Kdim + st*BKG);
        #pragma unroll
        for (int j = 0; j < 4; ++j)
            cp_async16(Bsw + st*BSTRIDE + j*4*BPITCH,
                       Bptr + (size_t)(st*BKG + j*4) * Ndim);
        CP_COMMIT();
    }

    int stage = 0;
    for (int i = 0; i < ntiles; ++i) {
        CP_WAIT1();
        __syncthreads();

        const float* Ast = As + stage * ASTRIDE;
        const float* Bst = Bs + stage * BSTRIDE;

        #pragma unroll
        for (int kk = 0; kk < 2; ++kk) {
            unsigned afr[4][4], bfr[8][2];
            #pragma unroll
            for (int mi = 0; mi < 4; ++mi) {
                const float* ab = Ast + (warp_m*64 + mi*16 + g) * APITCH + kk*8 + t;
                afr[mi][0] = __float_as_uint(ab[0]);
                afr[mi][1] = __float_as_uint(ab[8 * APITCH]);
                afr[mi][2] = __float_as_uint(ab[4]);
                afr[mi][3] = __float_as_uint(ab[8 * APITCH + 4]);
            }
            #pragma unroll
            for (int ni = 0; ni < 8; ++ni) {
                const float* bb = Bst + (kk*8 + t) * BPITCH + warp_n*64 + ni*8 + g;
                bfr[ni][0] = __float_as_uint(bb[0]);
                bfr[ni][1] = __float_as_uint(bb[4 * BPITCH]);
            }
            #pragma unroll
            for (int mi = 0; mi < 4; ++mi)
                #pragma unroll
                for (int ni = 0; ni < 8; ++ni)
                    mma_tf32(c[mi][ni], afr[mi], bfr[ni]);
        }

        __syncthreads();

        int nx = i + 2;
        if (nx < ntiles) {
            int ns = nx % NSTAGE;
            cp_async16(Asw + ns*ASTRIDE,             Aptr + nx*BKG);
            cp_async16(Asw + ns*ASTRIDE + 64*APITCH, Aptr + (size_t)64*Kdim + nx*BKG);
            #pragma unroll
            for (int j = 0; j < 4; ++j)
                cp_async16(Bsw + ns*BSTRIDE + j*4*BPITCH,
                           Bptr + (size_t)(nx*BKG + j*4) * Ndim);
        }
        CP_COMMIT();
        stage = (stage + 1 == NSTAGE) ? 0 : stage + 1;
    }

    // epilogue
    #pragma unroll
    for (int mi = 0; mi < 4; ++mi) {
        #pragma unroll
        for (int ni = 0; ni < 8; ++ni) {
            int row = m0 + warp_m*64 + mi*16 + g;
            int col = n0 + warp_n*64 + ni*8 + 2*t;
            float2 bb = *(const float2*)(bias + col);
            float2 o0, o1;
            o0.x = c[mi][ni][0] + bb.x; o0.y = c[mi][ni][1] + bb.y;
            o1.x = c[mi][ni][2] + bb.x; o1.y = c[mi][ni][3] + bb.y;
            *(float2*)(Cm + (size_t)row * Ndim + col) = o0;
            *(float2*)(Cm + (size_t)(row + 8) * Ndim + col) = o1;
        }
    }
}

// ---------------------------------------------------------------------------
// TF32 tensor-core flash attention, causal (unchanged from R5).
// ---------------------------------------------------------------------------
#define QTILE 128
#define KTILE 64
#define AP 68
#define VP 72
#define NEG_BIG (-1e30f)

__global__ __launch_bounds__(256)
void attn_tc_kernel(const float* __restrict__ qkv, float* __restrict__ Y)
{
    extern __shared__ float smf[];
    float* Qs = smf;
    float* Ks = Qs + QTILE * AP;
    float* Vs = Ks + KTILE * AP;
    float* Ps = Vs + KTILE * VP;

    const int bh = blockIdx.y;
    const int b  = bh >> 4;
    const int h  = bh & 15;
    const int q0 = blockIdx.x * QTILE;

    const int tid  = threadIdx.x;
    const int lane = tid & 31;
    const int wid  = tid >> 5;
    const int g    = lane >> 2;
    const int t    = lane & 3;
    const int wr   = wid * 16;

    const size_t tok_base = (size_t)b * TT * N_QKV;
    const float scale = 0.03125f;

    #pragma unroll
    for (int it = 0; it < 8; ++it) {
        int idx = tid + it * 256;
        int r = idx >> 4, q = idx & 15;
        float4 v = *(const float4*)(qkv + tok_base + (size_t)(q0 + r) * N_QKV + h*DD + 4*q);
        float* dst = Qs + r * AP + 4*q;
        dst[0] = to_tf32f(v.x); dst[1] = to_tf32f(v.y);
        dst[2] = to_tf32f(v.z); dst[3] = to_tf32f(v.w);
    }

    float o[8][4];
    #pragma unroll
    for (int n = 0; n < 8; ++n)
        #pragma unroll
        for (int j = 0; j < 4; ++j) o[n][j] = 0.f;
    float mrow[2] = {NEG_BIG, NEG_BIG};
    float lrow[2] = {0.f, 0.f};

    const int q_hi  = q0 + wr + 15;
    const int ktmax = (q0 + QTILE - 1) / KTILE;

    for (int kt = 0; kt <= ktmax; ++kt) {
        const int k0 = kt * KTILE;

        float4 kv[4], vv[4];
        #pragma unroll
        for (int it = 0; it < 4; ++it) {
            int idx = tid + it * 256;
            int r = idx >> 4, q = idx & 15;
            size_t rowb = tok_base + (size_t)(k0 + r) * N_QKV + h*DD + 4*q;
            kv[it] = *(const float4*)(qkv + rowb + CC);
            vv[it] = *(const float4*)(qkv + rowb + 2*CC);
        }
        __syncthreads();
        #pragma unroll
        for (int it = 0; it < 4; ++it) {
            int idx = tid + it * 256;
            int r = idx >> 4, q = idx & 15;
            float* kd = Ks + r * AP + 4*q;
            kd[0] = to_tf32f(kv[it].x); kd[1] = to_tf32f(kv[it].y);
            kd[2] = to_tf32f(kv[it].z); kd[3] = to_tf32f(kv[it].w);
            float* vd = Vs + r * VP + 4*q;
            vd[0] = to_tf32f(vv[it].x); vd[1] = to_tf32f(vv[it].y);
            vd[2] = to_tf32f(vv[it].z); vd[3] = to_tf32f(vv[it].w);
        }
        __syncthreads();

        if (k0 <= q_hi) {
            float s[8][4];
            #pragma unroll
            for (int n = 0; n < 8; ++n)
                #pragma unroll
                for (int j = 0; j < 4; ++j) s[n][j] = 0.f;

            #pragma unroll
            for (int kk = 0; kk < 8; ++kk) {
                unsigned qa[4];
                const float* qb = Qs + (wr + g) * AP + kk*8 + t;
                qa[0] = __float_as_uint(qb[0]);
                qa[1] = __float_as_uint(qb[8 * AP]);
                qa[2] = __float_as_uint(qb[4]);
                qa[3] = __float_as_uint(qb[8 * AP + 4]);
                #pragma unroll
                for (int n = 0; n < 8; ++n) {
                    unsigned bf[2];
                    const float* kb = Ks + (n*8 + g) * AP + kk*8 + t;
                    bf[0] = __float_as_uint(kb[0]);
                    bf[1] = __float_as_uint(kb[4]);
                    mma_tf32(s[n], qa, bf);
                }
            }

            #pragma unroll
            for (int n = 0; n < 8; ++n)
                #pragma unroll
                for (int j = 0; j < 4; ++j) s[n][j] *= scale;

            if (k0 + KTILE - 1 > q0 + wr) {
                int r0 = q0 + wr + g, r1 = r0 + 8;
                #pragma unroll
                for (int n = 0; n < 8; ++n) {
                    int key = k0 + n*8 + 2*t;
                    if (key     > r0) s[n][0] = NEG_BIG;
                    if (key + 1 > r0) s[n][1] = NEG_BIG;
                    if (key     > r1) s[n][2] = NEG_BIG;
                    if (key + 1 > r1) s[n][3] = NEG_BIG;
                }
            }

            #pragma unroll
            for (int half = 0; half < 2; ++half) {
                float rm = NEG_BIG;
                #pragma unroll
                for (int n = 0; n < 8; ++n)
                    rm = fmaxf(rm, fmaxf(s[n][2*half], s[n][2*half+1]));
                rm = fmaxf(rm, __shfl_xor_sync(0xffffffffu, rm, 1));
                rm = fmaxf(rm, __shfl_xor_sync(0xffffffffu, rm, 2));
                float mn = fmaxf(mrow[half], rm);
                float alpha = __expf(mrow[half] - mn);
                float ps = 0.f;
                #pragma unroll
                for (int n = 0; n < 8; ++n) {
                    float p0 = __expf(s[n][2*half]   - mn);
                    float p1 = __expf(s[n][2*half+1] - mn);
                    s[n][2*half] = p0; s[n][2*half+1] = p1;
                    ps += p0 + p1;
                }
                ps += __shfl_xor_sync(0xffffffffu, ps, 1);
                ps += __shfl_xor_sync(0xffffffffu, ps, 2);
                lrow[half] = lrow[half] * alpha + ps;
                mrow[half] = mn;
                #pragma unroll
                for (int n = 0; n < 8; ++n) {
                    o[n][2*half]   *= alpha;
                    o[n][2*half+1] *= alpha;
                }
            }

            #pragma unroll
            for (int n = 0; n < 8; ++n) {
                float* p0 = Ps + (wr + g) * AP + n*8 + 2*t;
                p0[0] = to_tf32f(s[n][0]); p0[1] = to_tf32f(s[n][1]);
                float* p1 = Ps + (wr + g + 8) * AP + n*8 + 2*t;
                p1[0] = to_tf32f(s[n][2]); p1[1] = to_tf32f(s[n][3]);
            }
            __syncwarp();

            #pragma unroll
            for (int kk = 0; kk < 8; ++kk) {
                unsigned pa[4];
                const float* pb = Ps + (wr + g) * AP + kk*8 + t;
                pa[0] = __float_as_uint(pb[0]);
                pa[1] = __float_as_uint(pb[8 * AP]);
                pa[2] = __float_as_uint(pb[4]);
                pa[3] = __float_as_uint(pb[8 * AP + 4]);
                #pragma unroll
                for (int n = 0; n < 8; ++n) {
                    unsigned bf[2];
                    const float* vb = Vs + (kk*8 + t) * VP + n*8 + g;
                    bf[0] = __float_as_uint(vb[0]);
                    bf[1] = __float_as_uint(vb[4 * VP]);
                    mma_tf32(o[n], pa, bf);
                }
            }
        }
    }

    #pragma unroll
    for (int half = 0; half < 2; ++half) {
        float inv = 1.0f / lrow[half];
        int row = q0 + wr + g + half * 8;
        float* yb = Y + (size_t)(b * TT + row) * CC + h*DD + 2*t;
        #pragma unroll
        for (int n = 0; n < 8; ++n) {
            float2 ov;
            ov.x = to_tf32f(o[n][2*half]   * inv);
            ov.y = to_tf32f(o[n][2*half+1] * inv);
            *(float2*)(yb + n*8) = ov;
        }
    }
}

// ---------------------------------------------------------------------------
// Launch
// ---------------------------------------------------------------------------
extern "C" void kernel_launch(void* const* d_in, const int* in_sizes, int n_in,
                              void* d_out, int out_size)
{
    const float* x      = (const float*)d_in[0];
    const float* W_attn = (const float*)d_in[1];
    const float* b_attn = (const float*)d_in[2];
    const float* W_proj = (const float*)d_in[3];
    const float* b_proj = (const float*)d_in[4];
    float* out = (float*)d_out;

    float *qkv_ptr, *y_ptr, *xr_ptr, *wa_ptr, *wp_ptr;
    cudaGetSymbolAddress((void**)&qkv_ptr, g_qkv);
    cudaGetSymbolAddress((void**)&y_ptr, g_y);
    cudaGetSymbolAddress((void**)&xr_ptr, g_xr);
    cudaGetSymbolAddress((void**)&wa_ptr, g_wa);
    cudaGetSymbolAddress((void**)&wp_ptr, g_wp);

    const int attn_smem = (QTILE*AP + KTILE*AP + KTILE*VP + QTILE*AP) * sizeof(float);
    cudaFuncSetAttribute(attn_tc_kernel, cudaFuncAttributeMaxDynamicSharedMemorySize, attn_smem);
    cudaFuncSetAttribute(gemm_tf32_pipe, cudaFuncAttributeMaxDynamicSharedMemorySize, GEMM_SMEM);

    // 0) tf32 rounding pre-pass
    {
        int n4 = M_TOK * CC / 4;
        round_tf32_kernel<<<(n4 + 255)/256, 256>>>(x, xr_ptr, n4);
        n4 = CC * N_QKV / 4;
        round_tf32_kernel<<<(n4 + 255)/256, 256>>>(W_attn, wa_ptr, n4);
        n4 = CC * CC / 4;
        round_tf32_kernel<<<(n4 + 255)/256, 256>>>(W_proj, wp_ptr, n4);
    }

    // 1) qkv = xr @ War + b_attn
    gemm_tf32_pipe<<<dim3(N_QKV/BN, M_TOK/BM), 256, GEMM_SMEM>>>(
        xr_ptr, wa_ptr, b_attn, qkv_ptr, M_TOK, N_QKV, CC);

    // 2) flash attention
    attn_tc_kernel<<<dim3(TT/QTILE, BB*HH), 256, attn_smem>>>(qkv_ptr, y_ptr);

    // 3) out = y @ Wpr + b_proj
    gemm_tf32_pipe<<<dim3(CC/BN, M_TOK/BM), 256, GEMM_SMEM>>>(
        y_ptr, wp_ptr, b_proj, out, M_TOK, CC, CC);
}

// round 10
// speedup vs baseline: 4.4555x; 1.4605x over previous
#include <cuda_runtime.h>
#include <cuda_fp16.h>
#include <math.h>
#include <stdint.h>

// Problem constants
#define BB 2
#define TT 2048
#define CC 1024
#define HH 16
#define DD 64
#define M_TOK (BB*TT)     // 4096
#define N_QKV (3*CC)      // 3072

// Scratch (allocation-free rule: __device__ globals)
__device__ __half g_qkv[M_TOK * N_QKV];  // 24 MB : fp16 qkv
__device__ __half g_y[M_TOK * CC];       //  8 MB : fp16 attention output
__device__ __half g_xh[M_TOK * CC];      //  8 MB : fp16 x
__device__ __half g_wa[N_QKV * CC];      //  6 MB : fp16 W_attn^T [N,K]
__device__ __half g_wp[CC * CC];         //  2 MB : fp16 W_proj^T [N,K]

// ---------------------------------------------------------------------------
// helpers
// ---------------------------------------------------------------------------
__device__ __forceinline__ unsigned pack_h2(float a, float b) {
    __half2 h = __floats2half2_rn(a, b);
    return *reinterpret_cast<unsigned*>(&h);
}

__device__ __forceinline__ void mma_h(float c[4], const unsigned a[4], const unsigned b[2]) {
    asm volatile(
        "mma.sync.aligned.m16n8k16.row.col.f32.f16.f16.f32 "
        "{%0,%1,%2,%3}, {%4,%5,%6,%7}, {%8,%9}, {%0,%1,%2,%3};\n"
        : "+f"(c[0]), "+f"(c[1]), "+f"(c[2]), "+f"(c[3])
        : "r"(a[0]), "r"(a[1]), "r"(a[2]), "r"(a[3]), "r"(b[0]), "r"(b[1]));
}

__device__ __forceinline__ void cp_async16(void* smem, const void* gmem) {
    unsigned saddr = (unsigned)__cvta_generic_to_shared(smem);
    asm volatile("cp.async.cg.shared.global [%0], [%1], 16;\n" :: "r"(saddr), "l"(gmem));
}
#define CP_COMMIT() asm volatile("cp.async.commit_group;\n" ::: "memory")
#define CP_WAIT1()  asm volatile("cp.async.wait_group 1;\n" ::: "memory")

// ---------------------------------------------------------------------------
// pre-pass kernels
// ---------------------------------------------------------------------------
__global__ void to_half_kernel(const float* __restrict__ in, unsigned* __restrict__ out, int n4)
{
    int i = blockIdx.x * blockDim.x + threadIdx.x;
    if (i < n4) {
        float4 v = ((const float4*)in)[i];
        uint2 o;
        o.x = pack_h2(v.x, v.y);
        o.y = pack_h2(v.z, v.w);
        ((uint2*)out)[i] = o;
    }
}

// out[n][k] = half(in[k][n]);  in: [K, N] row-major fp32
__global__ void transpose_h_kernel(const float* __restrict__ in, __half* __restrict__ out,
                                   int K, int N)
{
    __shared__ float tile[32][33];
    int k0 = blockIdx.y * 32, n0 = blockIdx.x * 32;
    int tx = threadIdx.x, ty = threadIdx.y;   // 32 x 8
    #pragma unroll
    for (int j = 0; j < 4; ++j)
        tile[ty + 8*j][tx] = in[(size_t)(k0 + ty + 8*j) * N + n0 + tx];
    __syncthreads();
    #pragma unroll
    for (int j = 0; j < 4; ++j)
        out[(size_t)(n0 + ty + 8*j) * K + k0 + tx] = __float2half_rn(tile[tx][ty + 8*j]);
}

// ---------------------------------------------------------------------------
// fp16 GEMM, 3-stage cp.async pipeline, 64x64 warp tiles.
// C[M,N] = A[M,K] @ Bt[N,K]^T + bias[N];  A,Bt fp16; acc fp32.
// BM=128, BN=256, BK=32, 256 threads (8 warps 2x4).
// OUTF32: 1 -> write fp32 C; 0 -> write fp16 C.
// ---------------------------------------------------------------------------
#define GBM 128
#define GBN 256
#define GBK 32
#define HNST 3
#define HAP 40                     // A pitch (halves): bank (20g+t) distinct
#define HBP 40                     // B pitch (halves)
#define HAST (GBM * HAP)           // 5120 halves / stage
#define HBST (GBN * HBP)           // 10240 halves / stage
#define GEMMH_SMEM ((HNST*(HAST + HBST)) * 2)   // 92160 B

template<int OUTF32>
__global__ __launch_bounds__(256)
void gemm_h(const __half* __restrict__ A, const __half* __restrict__ Bt,
            const float* __restrict__ bias, void* __restrict__ Cout,
            int Mdim, int Ndim, int Kdim)
{
    extern __shared__ __half hsm[];
    __half* As = hsm;                       // [HNST][GBM][HAP]
    __half* Bs = hsm + HNST * HAST;         // [HNST][GBN][HBP]

    const int tid  = threadIdx.x;
    const int lane = tid & 31;
    const int wid  = tid >> 5;
    const int g    = lane >> 2;
    const int t    = lane & 3;
    const int warp_m = wid & 1;
    const int warp_n = wid >> 1;
    const int m0 = blockIdx.y * GBM;
    const int n0 = blockIdx.x * GBN;

    // cp.async mapping: 16B = 8 halves per op
    const int arow = tid >> 2, au = tid & 3;   // A: 128 rows x 4 units; 2 ops (row, row+64)
    const int brow = tid >> 2, bu = tid & 3;   // B: 256 rows x 4 units; 4 ops (row+64j)

    const __half* Ap = A  + (size_t)(m0 + arow) * Kdim + 8 * au;
    const __half* Bp = Bt + (size_t)(n0 + brow) * Kdim + 8 * bu;

    __half* Asw = As + arow * HAP + 8 * au;
    __half* Bsw = Bs + brow * HBP + 8 * bu;

    float c[4][8][4];
    #pragma unroll
    for (int mi = 0; mi < 4; ++mi)
        #pragma unroll
        for (int ni = 0; ni < 8; ++ni)
            #pragma unroll
            for (int j = 0; j < 4; ++j) c[mi][ni][j] = 0.f;

    const int ntiles = Kdim / GBK;

    // prologue: fill stages 0,1
    #pragma unroll
    for (int st = 0; st < 2; ++st) {
        cp_async16(Asw + st*HAST,            Ap + st*GBK);
        cp_async16(Asw + st*HAST + 64*HAP,   Ap + (size_t)64*Kdim + st*GBK);
        #pragma unroll
        for (int j = 0; j < 4; ++j)
            cp_async16(Bsw + st*HBST + j*64*HBP,
                       Bp + (size_t)(j*64)*Kdim + st*GBK);
        CP_COMMIT();
    }

    int stage = 0;
    for (int i = 0; i < ntiles; ++i) {
        CP_WAIT1();
        __syncthreads();

        const __half* Ast = As + stage * HAST;
        const __half* Bst = Bs + stage * HBST;

        #pragma unroll
        for (int kk = 0; kk < 2; ++kk) {
            unsigned afr[4][4], bfr[8][2];
            #pragma unroll
            for (int mi = 0; mi < 4; ++mi) {
                const __half* ab = Ast + (warp_m*64 + mi*16 + g) * HAP + kk*16 + 2*t;
                afr[mi][0] = *(const unsigned*)(ab);
                afr[mi][1] = *(const unsigned*)(ab + 8*HAP);
                afr[mi][2] = *(const unsigned*)(ab + 8);
                afr[mi][3] = *(const unsigned*)(ab + 8*HAP + 8);
            }
            #pragma unroll
            for (int ni = 0; ni < 8; ++ni) {
                const __half* bb = Bst + (warp_n*64 + ni*8 + g) * HBP + kk*16 + 2*t;
                bfr[ni][0] = *(const unsigned*)(bb);
                bfr[ni][1] = *(const unsigned*)(bb + 8);
            }
            #pragma unroll
            for (int mi = 0; mi < 4; ++mi)
                #pragma unroll
                for (int ni = 0; ni < 8; ++ni)
                    mma_h(c[mi][ni], afr[mi], bfr[ni]);
        }

        __syncthreads();

        int nx = i + 2;
        if (nx < ntiles) {
            int ns = nx % HNST;
            cp_async16(Asw + ns*HAST,          Ap + nx*GBK);
            cp_async16(Asw + ns*HAST + 64*HAP, Ap + (size_t)64*Kdim + nx*GBK);
            #pragma unroll
            for (int j = 0; j < 4; ++j)
                cp_async16(Bsw + ns*HBST + j*64*HBP,
                           Bp + (size_t)(j*64)*Kdim + nx*GBK);
        }
        CP_COMMIT();
        stage = (stage + 1 == HNST) ? 0 : stage + 1;
    }

    // epilogue
    #pragma unroll
    for (int mi = 0; mi < 4; ++mi) {
        #pragma unroll
        for (int ni = 0; ni < 8; ++ni) {
            int row = m0 + warp_m*64 + mi*16 + g;
            int col = n0 + warp_n*64 + ni*8 + 2*t;
            float2 bb = *(const float2*)(bias + col);
            float v00 = c[mi][ni][0] + bb.x, v01 = c[mi][ni][1] + bb.y;
            float v10 = c[mi][ni][2] + bb.x, v11 = c[mi][ni][3] + bb.y;
            if (OUTF32) {
                float* Cf = (float*)Cout;
                float2 o0 = {v00, v01}, o1 = {v10, v11};
                *(float2*)(Cf + (size_t)row * Ndim + col) = o0;
                *(float2*)(Cf + (size_t)(row + 8) * Ndim + col) = o1;
            } else {
                __half* Ch = (__half*)Cout;
                *(unsigned*)(Ch + (size_t)row * Ndim + col) = pack_h2(v00, v01);
                *(unsigned*)(Ch + (size_t)(row + 8) * Ndim + col) = pack_h2(v10, v11);
            }
        }
    }
}

// ---------------------------------------------------------------------------
// fp16 tensor-core flash attention, causal.
// QTILE=128 rows/CTA, KTILE=64 keys/iter, 256 threads (8 warps x 16 rows).
// m16n8k16 fp16 mma; V stored transposed [d][key] in smem; softmax fp32.
// ---------------------------------------------------------------------------
#define QTILE 128
#define KTILE 64
#define HP 72                      // pitch (halves): bank (4g+t) distinct
#define NEG_BIG (-1e30f)

__global__ __launch_bounds__(256)
void attn_h_kernel(const __half* __restrict__ qkv, __half* __restrict__ Y)
{
    extern __shared__ __half smh[];
    __half* Qs = smh;                       // [128][HP]
    __half* Ks = Qs + QTILE * HP;           // [64][HP]   (key-major, d contiguous)
    __half* Vt = Ks + KTILE * HP;           // [64][HP]   (d-major, key contiguous)
    __half* Ps = Vt + KTILE * HP;           // [128][HP]

    const int bh = blockIdx.y;
    const int b  = bh >> 4;
    const int h  = bh & 15;
    const int q0 = blockIdx.x * QTILE;

    const int tid  = threadIdx.x;
    const int lane = tid & 31;
    const int wid  = tid >> 5;
    const int g    = lane >> 2;
    const int t    = lane & 3;
    const int wr   = wid * 16;

    const size_t tok_base = (size_t)b * TT * N_QKV;
    const float scale = 0.03125f;           // 1/sqrt(1024)

    // ---- load Q tile (128 rows x 64 halves), 16B chunks ----
    #pragma unroll
    for (int it = 0; it < 4; ++it) {
        int idx = tid + it * 256;           // 0..1023
        int r = idx >> 3, q8 = idx & 7;
        uint4 v = *(const uint4*)(qkv + tok_base + (size_t)(q0 + r) * N_QKV + h*DD + 8*q8);
        *(uint4*)(Qs + r * HP + 8*q8) = v;
    }

    float o[8][4];
    #pragma unroll
    for (int n = 0; n < 8; ++n)
        #pragma unroll
        for (int j = 0; j < 4; ++j) o[n][j] = 0.f;
    float mrow[2] = {NEG_BIG, NEG_BIG};
    float lrow[2] = {0.f, 0.f};

    const int q_hi  = q0 + wr + 15;
    const int ktmax = (q0 + QTILE - 1) / KTILE;

    for (int kt = 0; kt <= ktmax; ++kt) {
        const int k0 = kt * KTILE;

        // prefetch K,V (64 rows x 8 chunks each = 512 ops -> 2 iters)
        uint4 kv[2], vv[2];
        #pragma unroll
        for (int it = 0; it < 2; ++it) {
            int idx = tid + it * 256;
            int r = idx >> 3, q8 = idx & 7;
            size_t rowb = tok_base + (size_t)(k0 + r) * N_QKV + h*DD + 8*q8;
            kv[it] = *(const uint4*)(qkv + rowb + CC);
            vv[it] = *(const uint4*)(qkv + rowb + 2*CC);
        }
        __syncthreads();
        #pragma unroll
        for (int it = 0; it < 2; ++it) {
            int idx = tid + it * 256;
            int r = idx >> 3, q8 = idx & 7;
            *(uint4*)(Ks + r * HP + 8*q8) = kv[it];
            // V transposed: element d = 8*q8+j, key = r
            const __half* vh = (const __half*)&vv[it];
            #pragma unroll
            for (int j = 0; j < 8; ++j)
                Vt[(8*q8 + j) * HP + r] = vh[j];
        }
        __syncthreads();

        if (k0 <= q_hi) {
            // ---- S = Q K^T  (4 k16 steps over d=64) ----
            float s[8][4];
            #pragma unroll
            for (int n = 0; n < 8; ++n)
                #pragma unroll
                for (int j = 0; j < 4; ++j) s[n][j] = 0.f;

            #pragma unroll
            for (int kk = 0; kk < 4; ++kk) {
                unsigned qa[4];
                const __half* qb = Qs + (wr + g) * HP + kk*16 + 2*t;
                qa[0] = *(const unsigned*)(qb);
                qa[1] = *(const unsigned*)(qb + 8*HP);
                qa[2] = *(const unsigned*)(qb + 8);
                qa[3] = *(const unsigned*)(qb + 8*HP + 8);
                #pragma unroll
                for (int n = 0; n < 8; ++n) {
                    unsigned bf[2];
                    const __half* kb = Ks + (n*8 + g) * HP + kk*16 + 2*t;
                    bf[0] = *(const unsigned*)(kb);
                    bf[1] = *(const unsigned*)(kb + 8);
                    mma_h(s[n], qa, bf);
                }
            }

            #pragma unroll
            for (int n = 0; n < 8; ++n)
                #pragma unroll
                for (int j = 0; j < 4; ++j) s[n][j] *= scale;

            // causal mask (diagonal region only)
            if (k0 + KTILE - 1 > q0 + wr) {
                int r0 = q0 + wr + g, r1 = r0 + 8;
                #pragma unroll
                for (int n = 0; n < 8; ++n) {
                    int key = k0 + n*8 + 2*t;
                    if (key     > r0) s[n][0] = NEG_BIG;
                    if (key + 1 > r0) s[n][1] = NEG_BIG;
                    if (key     > r1) s[n][2] = NEG_BIG;
                    if (key + 1 > r1) s[n][3] = NEG_BIG;
                }
            }

            // ---- online softmax (rows g and g+8) ----
            #pragma unroll
            for (int half = 0; half < 2; ++half) {
                float rm = NEG_BIG;
                #pragma unroll
                for (int n = 0; n < 8; ++n)
                    rm = fmaxf(rm, fmaxf(s[n][2*half], s[n][2*half+1]));
                rm = fmaxf(rm, __shfl_xor_sync(0xffffffffu, rm, 1));
                rm = fmaxf(rm, __shfl_xor_sync(0xffffffffu, rm, 2));
                float mn = fmaxf(mrow[half], rm);
                float alpha = __expf(mrow[half] - mn);
                float ps = 0.f;
                #pragma unroll
                for (int n = 0; n < 8; ++n) {
                    float p0 = __expf(s[n][2*half]   - mn);
                    float p1 = __expf(s[n][2*half+1] - mn);
                    s[n][2*half] = p0; s[n][2*half+1] = p1;
                    ps += p0 + p1;
                }
                ps += __shfl_xor_sync(0xffffffffu, ps, 1);
                ps += __shfl_xor_sync(0xffffffffu, ps, 2);
                lrow[half] = lrow[half] * alpha + ps;
                mrow[half] = mn;
                #pragma unroll
                for (int n = 0; n < 8; ++n) {
                    o[n][2*half]   *= alpha;
                    o[n][2*half+1] *= alpha;
                }
            }

            // ---- stage P (fp16) ----
            #pragma unroll
            for (int n = 0; n < 8; ++n) {
                *(unsigned*)(Ps + (wr + g) * HP + n*8 + 2*t)     = pack_h2(s[n][0], s[n][1]);
                *(unsigned*)(Ps + (wr + g + 8) * HP + n*8 + 2*t) = pack_h2(s[n][2], s[n][3]);
            }
            __syncwarp();

            // ---- O += P V  (4 k16 steps over keys=64) ----
            #pragma unroll
            for (int kk = 0; kk < 4; ++kk) {
                unsigned pa[4];
                const __half* pb = Ps + (wr + g) * HP + kk*16 + 2*t;
                pa[0] = *(const unsigned*)(pb);
                pa[1] = *(const unsigned*)(pb + 8*HP);
                pa[2] = *(const unsigned*)(pb + 8);
                pa[3] = *(const unsigned*)(pb + 8*HP + 8);
                #pragma unroll
                for (int n = 0; n < 8; ++n) {
                    unsigned bf[2];
                    const __half* vb = Vt + (n*8 + g) * HP + kk*16 + 2*t;
                    bf[0] = *(const unsigned*)(vb);
                    bf[1] = *(const unsigned*)(vb + 8);
                    mma_h(o[n], pa, bf);
                }
            }
        }
    }

    // ---- normalize + store fp16 y ----
    #pragma unroll
    for (int half = 0; half < 2; ++half) {
        float inv = 1.0f / lrow[half];
        int row = q0 + wr + g + half * 8;
        __half* yb = Y + (size_t)(b * TT + row) * CC + h*DD + 2*t;
        #pragma unroll
        for (int n = 0; n < 8; ++n)
            *(unsigned*)(yb + n*8) = pack_h2(o[n][2*half] * inv, o[n][2*half+1] * inv);
    }
}

#define ATTN_SMEM ((QTILE*HP + KTILE*HP + KTILE*HP + QTILE*HP) * 2)   // 55296 B

// ---------------------------------------------------------------------------
// Launch
// ---------------------------------------------------------------------------
extern "C" void kernel_launch(void* const* d_in, const int* in_sizes, int n_in,
                              void* d_out, int out_size)
{
    const float* x      = (const float*)d_in[0];
    const float* W_attn = (const float*)d_in[1];
    const float* b_attn = (const float*)d_in[2];
    const float* W_proj = (const float*)d_in[3];
    const float* b_proj = (const float*)d_in[4];
    float* out = (float*)d_out;

    __half *qkv_ptr, *y_ptr, *xh_ptr, *wa_ptr, *wp_ptr;
    cudaGetSymbolAddress((void**)&qkv_ptr, g_qkv);
    cudaGetSymbolAddress((void**)&y_ptr, g_y);
    cudaGetSymbolAddress((void**)&xh_ptr, g_xh);
    cudaGetSymbolAddress((void**)&wa_ptr, g_wa);
    cudaGetSymbolAddress((void**)&wp_ptr, g_wp);

    cudaFuncSetAttribute(attn_h_kernel, cudaFuncAttributeMaxDynamicSharedMemorySize, ATTN_SMEM);
    cudaFuncSetAttribute(gemm_h<0>, cudaFuncAttributeMaxDynamicSharedMemorySize, GEMMH_SMEM);
    cudaFuncSetAttribute(gemm_h<1>, cudaFuncAttributeMaxDynamicSharedMemorySize, GEMMH_SMEM);

    // 0) pre-pass: x -> fp16; weights -> fp16 transposed [N,K]
    {
        int n4 = M_TOK * CC / 4;
        to_half_kernel<<<(n4 + 255)/256, 256>>>(x, (unsigned*)xh_ptr, n4);
        transpose_h_kernel<<<dim3(N_QKV/32, CC/32), dim3(32, 8)>>>(W_attn, wa_ptr, CC, N_QKV);
        transpose_h_kernel<<<dim3(CC/32, CC/32), dim3(32, 8)>>>(W_proj, wp_ptr, CC, CC);
    }

    // 1) qkv = x @ W_attn + b_attn   (fp16 out)
    gemm_h<0><<<dim3(N_QKV/GBN, M_TOK/GBM), 256, GEMMH_SMEM>>>(
        xh_ptr, wa_ptr, b_attn, qkv_ptr, M_TOK, N_QKV, CC);

    // 2) flash attention (fp16)
    attn_h_kernel<<<dim3(TT/QTILE, BB*HH), 256, ATTN_SMEM>>>(qkv_ptr, y_ptr);

    // 3) out = y @ W_proj + b_proj   (fp32 out)
    gemm_h<1><<<dim3(CC/GBN, M_TOK/GBM), 256, GEMMH_SMEM>>>(
        y_ptr, wp_ptr, b_proj, out, M_TOK, CC, CC);
}

// round 11
// speedup vs baseline: 5.5230x; 1.2396x over previous
#include <cuda_runtime.h>
#include <cuda_fp16.h>
#include <math.h>
#include <stdint.h>

// Problem constants
#define BB 2
#define TT 2048
#define CC 1024
#define HH 16
#define DD 64
#define M_TOK (BB*TT)     // 4096
#define N_QKV (3*CC)      // 3072

// Scratch (allocation-free rule: __device__ globals)
__device__ __half g_qkv[M_TOK * N_QKV];  // 24 MB : fp16 qkv
__device__ __half g_y[M_TOK * CC];       //  8 MB : fp16 attention output
__device__ __half g_xh[M_TOK * CC];      //  8 MB : fp16 x
__device__ __half g_wa[N_QKV * CC];      //  6 MB : fp16 W_attn^T [N,K]
__device__ __half g_wp[CC * CC];         //  2 MB : fp16 W_proj^T [N,K]

// ---------------------------------------------------------------------------
// helpers
// ---------------------------------------------------------------------------
__device__ __forceinline__ unsigned pack_h2(float a, float b) {
    __half2 h = __floats2half2_rn(a, b);
    return *reinterpret_cast<unsigned*>(&h);
}

__device__ __forceinline__ void mma_h(float c[4], const unsigned a[4], const unsigned b[2]) {
    asm volatile(
        "mma.sync.aligned.m16n8k16.row.col.f32.f16.f16.f32 "
        "{%0,%1,%2,%3}, {%4,%5,%6,%7}, {%8,%9}, {%0,%1,%2,%3};\n"
        : "+f"(c[0]), "+f"(c[1]), "+f"(c[2]), "+f"(c[3])
        : "r"(a[0]), "r"(a[1]), "r"(a[2]), "r"(a[3]), "r"(b[0]), "r"(b[1]));
}

__device__ __forceinline__ void ldm_x4(unsigned& r0, unsigned& r1, unsigned& r2, unsigned& r3,
                                       uint32_t addr) {
    asm volatile("ldmatrix.sync.aligned.m8n8.x4.shared.b16 {%0,%1,%2,%3}, [%4];"
                 : "=r"(r0), "=r"(r1), "=r"(r2), "=r"(r3) : "r"(addr));
}
__device__ __forceinline__ void ldm_x4_t(unsigned& r0, unsigned& r1, unsigned& r2, unsigned& r3,
                                         uint32_t addr) {
    asm volatile("ldmatrix.sync.aligned.m8n8.x4.trans.shared.b16 {%0,%1,%2,%3}, [%4];"
                 : "=r"(r0), "=r"(r1), "=r"(r2), "=r"(r3) : "r"(addr));
}

__device__ __forceinline__ void cp_async16(void* smem, const void* gmem) {
    unsigned saddr = (unsigned)__cvta_generic_to_shared(smem);
    asm volatile("cp.async.cg.shared.global [%0], [%1], 16;\n" :: "r"(saddr), "l"(gmem));
}
#define CP_COMMIT() asm volatile("cp.async.commit_group;\n" ::: "memory")
#define CP_WAIT1()  asm volatile("cp.async.wait_group 1;\n" ::: "memory")

// ---------------------------------------------------------------------------
// pre-pass kernels
// ---------------------------------------------------------------------------
__global__ void to_half_kernel(const float* __restrict__ in, unsigned* __restrict__ out, int n4)
{
    int i = blockIdx.x * blockDim.x + threadIdx.x;
    if (i < n4) {
        float4 v = ((const float4*)in)[i];
        uint2 o;
        o.x = pack_h2(v.x, v.y);
        o.y = pack_h2(v.z, v.w);
        ((uint2*)out)[i] = o;
    }
}

// out[n][k] = half(in[k][n]);  in: [K, N] row-major fp32
__global__ void transpose_h_kernel(const float* __restrict__ in, __half* __restrict__ out,
                                   int K, int N)
{
    __shared__ float tile[32][33];
    int k0 = blockIdx.y * 32, n0 = blockIdx.x * 32;
    int tx = threadIdx.x, ty = threadIdx.y;   // 32 x 8
    #pragma unroll
    for (int j = 0; j < 4; ++j)
        tile[ty + 8*j][tx] = in[(size_t)(k0 + ty + 8*j) * N + n0 + tx];
    __syncthreads();
    #pragma unroll
    for (int j = 0; j < 4; ++j)
        out[(size_t)(n0 + ty + 8*j) * K + k0 + tx] = __float2half_rn(tile[tx][ty + 8*j]);
}

// ---------------------------------------------------------------------------
// fp16 GEMM, 3-stage cp.async pipeline, 64x64 warp tiles (unchanged from R10).
// ---------------------------------------------------------------------------
#define GBM 128
#define GBN 256
#define GBK 32
#define HNST 3
#define HAP 40
#define HBP 40
#define HAST (GBM * HAP)
#define HBST (GBN * HBP)
#define GEMMH_SMEM ((HNST*(HAST + HBST)) * 2)   // 92160 B

template<int OUTF32>
__global__ __launch_bounds__(256)
void gemm_h(const __half* __restrict__ A, const __half* __restrict__ Bt,
            const float* __restrict__ bias, void* __restrict__ Cout,
            int Mdim, int Ndim, int Kdim)
{
    extern __shared__ __half hsm[];
    __half* As = hsm;
    __half* Bs = hsm + HNST * HAST;

    const int tid  = threadIdx.x;
    const int lane = tid & 31;
    const int wid  = tid >> 5;
    const int g    = lane >> 2;
    const int t    = lane & 3;
    const int warp_m = wid & 1;
    const int warp_n = wid >> 1;
    const int m0 = blockIdx.y * GBM;
    const int n0 = blockIdx.x * GBN;

    const int arow = tid >> 2, au = tid & 3;
    const int brow = tid >> 2, bu = tid & 3;

    const __half* Ap = A  + (size_t)(m0 + arow) * Kdim + 8 * au;
    const __half* Bp = Bt + (size_t)(n0 + brow) * Kdim + 8 * bu;

    __half* Asw = As + arow * HAP + 8 * au;
    __half* Bsw = Bs + brow * HBP + 8 * bu;

    float c[4][8][4];
    #pragma unroll
    for (int mi = 0; mi < 4; ++mi)
        #pragma unroll
        for (int ni = 0; ni < 8; ++ni)
            #pragma unroll
            for (int j = 0; j < 4; ++j) c[mi][ni][j] = 0.f;

    const int ntiles = Kdim / GBK;

    #pragma unroll
    for (int st = 0; st < 2; ++st) {
        cp_async16(Asw + st*HAST,            Ap + st*GBK);
        cp_async16(Asw + st*HAST + 64*HAP,   Ap + (size_t)64*Kdim + st*GBK);
        #pragma unroll
        for (int j = 0; j < 4; ++j)
            cp_async16(Bsw + st*HBST + j*64*HBP,
                       Bp + (size_t)(j*64)*Kdim + st*GBK);
        CP_COMMIT();
    }

    int stage = 0;
    for (int i = 0; i < ntiles; ++i) {
        CP_WAIT1();
        __syncthreads();

        const __half* Ast = As + stage * HAST;
        const __half* Bst = Bs + stage * HBST;

        #pragma unroll
        for (int kk = 0; kk < 2; ++kk) {
            unsigned afr[4][4], bfr[8][2];
            #pragma unroll
            for (int mi = 0; mi < 4; ++mi) {
                const __half* ab = Ast + (warp_m*64 + mi*16 + g) * HAP + kk*16 + 2*t;
                afr[mi][0] = *(const unsigned*)(ab);
                afr[mi][1] = *(const unsigned*)(ab + 8*HAP);
                afr[mi][2] = *(const unsigned*)(ab + 8);
                afr[mi][3] = *(const unsigned*)(ab + 8*HAP + 8);
            }
            #pragma unroll
            for (int ni = 0; ni < 8; ++ni) {
                const __half* bb = Bst + (warp_n*64 + ni*8 + g) * HBP + kk*16 + 2*t;
                bfr[ni][0] = *(const unsigned*)(bb);
                bfr[ni][1] = *(const unsigned*)(bb + 8);
            }
            #pragma unroll
            for (int mi = 0; mi < 4; ++mi)
                #pragma unroll
                for (int ni = 0; ni < 8; ++ni)
                    mma_h(c[mi][ni], afr[mi], bfr[ni]);
        }

        __syncthreads();

        int nx = i + 2;
        if (nx < ntiles) {
            int ns = nx % HNST;
            cp_async16(Asw + ns*HAST,          Ap + nx*GBK);
            cp_async16(Asw + ns*HAST + 64*HAP, Ap + (size_t)64*Kdim + nx*GBK);
            #pragma unroll
            for (int j = 0; j < 4; ++j)
                cp_async16(Bsw + ns*HBST + j*64*HBP,
                           Bp + (size_t)(j*64)*Kdim + nx*GBK);
        }
        CP_COMMIT();
        stage = (stage + 1 == HNST) ? 0 : stage + 1;
    }

    #pragma unroll
    for (int mi = 0; mi < 4; ++mi) {
        #pragma unroll
        for (int ni = 0; ni < 8; ++ni) {
            int row = m0 + warp_m*64 + mi*16 + g;
            int col = n0 + warp_n*64 + ni*8 + 2*t;
            float2 bb = *(const float2*)(bias + col);
            float v00 = c[mi][ni][0] + bb.x, v01 = c[mi][ni][1] + bb.y;
            float v10 = c[mi][ni][2] + bb.x, v11 = c[mi][ni][3] + bb.y;
            if (OUTF32) {
                float* Cf = (float*)Cout;
                float2 o0 = {v00, v01}, o1 = {v10, v11};
                *(float2*)(Cf + (size_t)row * Ndim + col) = o0;
                *(float2*)(Cf + (size_t)(row + 8) * Ndim + col) = o1;
            } else {
                __half* Ch = (__half*)Cout;
                *(unsigned*)(Ch + (size_t)row * Ndim + col) = pack_h2(v00, v01);
                *(unsigned*)(Ch + (size_t)(row + 8) * Ndim + col) = pack_h2(v10, v11);
            }
        }
    }
}

// ---------------------------------------------------------------------------
// fp16 flash attention v2: ldmatrix fragments, P-in-registers, 2-stage cp.async.
// QTILE=128 rows/CTA, KTILE=64 keys/iter, 256 threads (8 warps x 16 rows).
// ---------------------------------------------------------------------------
#define QTILE 128
#define KTILE 64
#define HP 72                      // pitch (halves); row stride 144B -> ldmatrix conflict-free
#define NEG_BIG (-1e30f)
#define KVSTR (KTILE*HP*2)         // bytes per K/V stage = 9216
#define ATTN_SMEM ((QTILE*HP + 2*KTILE*HP + 2*KTILE*HP) * 2)   // 55296 B

__global__ __launch_bounds__(256)
void attn_h2_kernel(const __half* __restrict__ qkv, __half* __restrict__ Y)
{
    extern __shared__ __half smh[];
    __half* Qs  = smh;                      // [128][HP]
    __half* Kst = Qs + QTILE * HP;          // [2][64][HP] key-major
    __half* Vst = Kst + 2 * KTILE * HP;     // [2][64][HP] key-major (trans at ldmatrix)

    const int bh = blockIdx.y;
    const int b  = bh >> 4;
    const int h  = bh & 15;
    const int q0 = blockIdx.x * QTILE;

    const int tid  = threadIdx.x;
    const int lane = tid & 31;
    const int wid  = tid >> 5;
    const int g    = lane >> 2;
    const int t    = lane & 3;
    const int wr   = wid * 16;

    const uint32_t qb32 = (uint32_t)__cvta_generic_to_shared(Qs);
    const uint32_t kb32 = (uint32_t)__cvta_generic_to_shared(Kst);
    const uint32_t vb32 = (uint32_t)__cvta_generic_to_shared(Vst);

    // per-lane ldmatrix address components
    const int grp = lane >> 3, l7 = lane & 7;
    const uint32_t qoff = ((uint32_t)(wr + (lane & 15)) * HP + (uint32_t)(lane >> 4) * 8) * 2;
    const uint32_t koff = ((uint32_t)((grp >> 1) * 8 + l7) * HP) * 2 + (uint32_t)(grp & 1) * 16;
    const uint32_t voff = ((uint32_t)((grp & 1) * 8 + l7) * HP) * 2 + (uint32_t)(grp >> 1) * 16;

    const size_t tok_base = (size_t)b * TT * N_QKV;
    const float scale = 0.03125f;           // 1/sqrt(1024)

    const int q_hi  = q0 + wr + 15;
    const int ktmax = (q0 + QTILE - 1) / KTILE;

    // ---- prologue: group 0 = Q tile + K/V tile 0 ----
    #pragma unroll
    for (int it = 0; it < 4; ++it) {
        int idx = tid + it * 256;           // 0..1023
        int r = idx >> 3, q8 = idx & 7;
        cp_async16(Qs + r * HP + 8*q8,
                   qkv + tok_base + (size_t)(q0 + r) * N_QKV + h*DD + 8*q8);
    }
    #pragma unroll
    for (int it = 0; it < 2; ++it) {
        int idx = tid + it * 256;           // 0..511
        int r = idx >> 3, q8 = idx & 7;
        size_t rowb = tok_base + (size_t)r * N_QKV + h*DD + 8*q8;
        cp_async16(Kst + r * HP + 8*q8, qkv + rowb + CC);
        cp_async16(Vst + r * HP + 8*q8, qkv + rowb + 2*CC);
    }
    CP_COMMIT();
    // group 1 = K/V tile 1 (if any)
    if (ktmax >= 1) {
        #pragma unroll
        for (int it = 0; it < 2; ++it) {
            int idx = tid + it * 256;
            int r = idx >> 3, q8 = idx & 7;
            size_t rowb = tok_base + (size_t)(KTILE + r) * N_QKV + h*DD + 8*q8;
            cp_async16(Kst + KTILE*HP + r * HP + 8*q8, qkv + rowb + CC);
            cp_async16(Vst + KTILE*HP + r * HP + 8*q8, qkv + rowb + 2*CC);
        }
    }
    CP_COMMIT();
    CP_WAIT1();                              // group 0 (Q + tile 0) resident
    __syncthreads();

    // ---- Q fragments to registers (kept for whole kernel) ----
    unsigned qa[4][4];
    #pragma unroll
    for (int kk = 0; kk < 4; ++kk)
        ldm_x4(qa[kk][0], qa[kk][1], qa[kk][2], qa[kk][3], qb32 + qoff + kk*32);

    float o[8][4];
    #pragma unroll
    for (int n = 0; n < 8; ++n)
        #pragma unroll
        for (int j = 0; j < 4; ++j) o[n][j] = 0.f;
    float mrow[2] = {NEG_BIG, NEG_BIG};
    float lrow[2] = {0.f, 0.f};

    for (int kt = 0; kt <= ktmax; ++kt) {
        const int k0 = kt * KTILE;
        const uint32_t kbase = kb32 + (uint32_t)(kt & 1) * KVSTR;
        const uint32_t vbase = vb32 + (uint32_t)(kt & 1) * KVSTR;

        if (k0 <= q_hi) {
            // ---- S = Q K^T ----
            float s[8][4];
            #pragma unroll
            for (int n = 0; n < 8; ++n)
                #pragma unroll
                for (int j = 0; j < 4; ++j) s[n][j] = 0.f;

            #pragma unroll
            for (int kk = 0; kk < 4; ++kk) {
                #pragma unroll
                for (int p = 0; p < 4; ++p) {
                    unsigned r0, r1, r2, r3;
                    ldm_x4(r0, r1, r2, r3, kbase + koff + (uint32_t)p * (16*HP*2) + kk*32);
                    unsigned b0[2] = {r0, r1}, b1[2] = {r2, r3};
                    mma_h(s[2*p],     qa[kk], b0);
                    mma_h(s[2*p + 1], qa[kk], b1);
                }
            }

            #pragma unroll
            for (int n = 0; n < 8; ++n)
                #pragma unroll
                for (int j = 0; j < 4; ++j) s[n][j] *= scale;

            // causal mask (diagonal region only)
            if (k0 + KTILE - 1 > q0 + wr) {
                int r0q = q0 + wr + g, r1q = r0q + 8;
                #pragma unroll
                for (int n = 0; n < 8; ++n) {
                    int key = k0 + n*8 + 2*t;
                    if (key     > r0q) s[n][0] = NEG_BIG;
                    if (key + 1 > r0q) s[n][1] = NEG_BIG;
                    if (key     > r1q) s[n][2] = NEG_BIG;
                    if (key + 1 > r1q) s[n][3] = NEG_BIG;
                }
            }

            // ---- online softmax (rows g and g+8) ----
            #pragma unroll
            for (int half = 0; half < 2; ++half) {
                float rm = NEG_BIG;
                #pragma unroll
                for (int n = 0; n < 8; ++n)
                    rm = fmaxf(rm, fmaxf(s[n][2*half], s[n][2*half+1]));
                rm = fmaxf(rm, __shfl_xor_sync(0xffffffffu, rm, 1));
                rm = fmaxf(rm, __shfl_xor_sync(0xffffffffu, rm, 2));
                float mn = fmaxf(mrow[half], rm);
                float alpha = __expf(mrow[half] - mn);
                float ps = 0.f;
                #pragma unroll
                for (int n = 0; n < 8; ++n) {
                    float p0 = __expf(s[n][2*half]   - mn);
                    float p1 = __expf(s[n][2*half+1] - mn);
                    s[n][2*half] = p0; s[n][2*half+1] = p1;
                    ps += p0 + p1;
                }
                ps += __shfl_xor_sync(0xffffffffu, ps, 1);
                ps += __shfl_xor_sync(0xffffffffu, ps, 2);
                lrow[half] = lrow[half] * alpha + ps;
                mrow[half] = mn;
                #pragma unroll
                for (int n = 0; n < 8; ++n) {
                    o[n][2*half]   *= alpha;
                    o[n][2*half+1] *= alpha;
                }
            }

            // ---- O += P V : P directly from S registers ----
            #pragma unroll
            for (int kk = 0; kk < 4; ++kk) {
                unsigned pa[4];
                pa[0] = pack_h2(s[2*kk][0],     s[2*kk][1]);
                pa[1] = pack_h2(s[2*kk][2],     s[2*kk][3]);
                pa[2] = pack_h2(s[2*kk + 1][0], s[2*kk + 1][1]);
                pa[3] = pack_h2(s[2*kk + 1][2], s[2*kk + 1][3]);
                #pragma unroll
                for (int p = 0; p < 4; ++p) {
                    unsigned r0, r1, r2, r3;
                    ldm_x4_t(r0, r1, r2, r3, vbase + voff + (uint32_t)kk * (16*HP*2) + p*32);
                    unsigned b0[2] = {r0, r1}, b1[2] = {r2, r3};
                    mma_h(o[2*p],     pa, b0);
                    mma_h(o[2*p + 1], pa, b1);
                }
            }
        }

        __syncthreads();     // all warps done reading stage kt&1 before refill

        if (kt + 2 <= ktmax) {
            int k0n = (kt + 2) * KTILE;
            int st = kt & 1;
            #pragma unroll
            for (int it = 0; it < 2; ++it) {
                int idx = tid + it * 256;
                int r = idx >> 3, q8 = idx & 7;
                size_t rowb = tok_base + (size_t)(k0n + r) * N_QKV + h*DD + 8*q8;
                cp_async16(Kst + st*KTILE*HP + r * HP + 8*q8, qkv + rowb + CC);
                cp_async16(Vst + st*KTILE*HP + r * HP + 8*q8, qkv + rowb + 2*CC);
            }
        }
        CP_COMMIT();
        CP_WAIT1();          // tile kt+1 resident
        __syncthreads();
    }

    // ---- normalize + store fp16 y ----
    #pragma unroll
    for (int half = 0; half < 2; ++half) {
        float inv = 1.0f / lrow[half];
        int row = q0 + wr + g + half * 8;
        __half* yb = Y + (size_t)(b * TT + row) * CC + h*DD + 2*t;
        #pragma unroll
        for (int n = 0; n < 8; ++n)
            *(unsigned*)(yb + n*8) = pack_h2(o[n][2*half] * inv, o[n][2*half+1] * inv);
    }
}

// ---------------------------------------------------------------------------
// Launch
// ---------------------------------------------------------------------------
extern "C" void kernel_launch(void* const* d_in, const int* in_sizes, int n_in,
                              void* d_out, int out_size)
{
    const float* x      = (const float*)d_in[0];
    const float* W_attn = (const float*)d_in[1];
    const float* b_attn = (const float*)d_in[2];
    const float* W_proj = (const float*)d_in[3];
    const float* b_proj = (const float*)d_in[4];
    float* out = (float*)d_out;

    __half *qkv_ptr, *y_ptr, *xh_ptr, *wa_ptr, *wp_ptr;
    cudaGetSymbolAddress((void**)&qkv_ptr, g_qkv);
    cudaGetSymbolAddress((void**)&y_ptr, g_y);
    cudaGetSymbolAddress((void**)&xh_ptr, g_xh);
    cudaGetSymbolAddress((void**)&wa_ptr, g_wa);
    cudaGetSymbolAddress((void**)&wp_ptr, g_wp);

    cudaFuncSetAttribute(attn_h2_kernel, cudaFuncAttributeMaxDynamicSharedMemorySize, ATTN_SMEM);
    cudaFuncSetAttribute(gemm_h<0>, cudaFuncAttributeMaxDynamicSharedMemorySize, GEMMH_SMEM);
    cudaFuncSetAttribute(gemm_h<1>, cudaFuncAttributeMaxDynamicSharedMemorySize, GEMMH_SMEM);

    // 0) pre-pass: x -> fp16; weights -> fp16 transposed [N,K]
    {
        int n4 = M_TOK * CC / 4;
        to_half_kernel<<<(n4 + 255)/256, 256>>>(x, (unsigned*)xh_ptr, n4);
        transpose_h_kernel<<<dim3(N_QKV/32, CC/32), dim3(32, 8)>>>(W_attn, wa_ptr, CC, N_QKV);
        transpose_h_kernel<<<dim3(CC/32, CC/32), dim3(32, 8)>>>(W_proj, wp_ptr, CC, CC);
    }

    // 1) qkv = x @ W_attn + b_attn   (fp16 out)
    gemm_h<0><<<dim3(N_QKV/GBN, M_TOK/GBM), 256, GEMMH_SMEM>>>(
        xh_ptr, wa_ptr, b_attn, qkv_ptr, M_TOK, N_QKV, CC);

    // 2) flash attention v2 (fp16, ldmatrix + cp.async)
    attn_h2_kernel<<<dim3(TT/QTILE, BB*HH), 256, ATTN_SMEM>>>(qkv_ptr, y_ptr);

    // 3) out = y @ W_proj + b_proj   (fp32 out)
    gemm_h<1><<<dim3(CC/GBN, M_TOK/GBM), 256, GEMMH_SMEM>>>(
        y_ptr, wp_ptr, b_proj, out, M_TOK, CC, CC);
}

// round 14
// speedup vs baseline: 5.8837x; 1.0653x over previous
#include <cuda_runtime.h>
#include <cuda_fp16.h>
#include <math.h>
#include <stdint.h>

// Problem constants
#define BB 2
#define TT 2048
#define CC 1024
#define HH 16
#define DD 64
#define M_TOK (BB*TT)     // 4096
#define N_QKV (3*CC)      // 3072

// Scratch (allocation-free rule: __device__ globals)
__device__ __half g_qkv[M_TOK * N_QKV];  // 24 MB
__device__ __half g_y[M_TOK * CC];       //  8 MB
__device__ __half g_xh[M_TOK * CC];      //  8 MB
__device__ __half g_wa[N_QKV * CC];      //  6 MB : W_attn^T [N,K]
__device__ __half g_wp[CC * CC];         //  2 MB : W_proj^T [N,K]

// ---------------------------------------------------------------------------
// helpers
// ---------------------------------------------------------------------------
__device__ __forceinline__ unsigned pack_h2(float a, float b) {
    __half2 h = __floats2half2_rn(a, b);
    return *reinterpret_cast<unsigned*>(&h);
}

__device__ __forceinline__ void mma_h(float c[4], const unsigned a[4], const unsigned b[2]) {
    asm volatile(
        "mma.sync.aligned.m16n8k16.row.col.f32.f16.f16.f32 "
        "{%0,%1,%2,%3}, {%4,%5,%6,%7}, {%8,%9}, {%0,%1,%2,%3};\n"
        : "+f"(c[0]), "+f"(c[1]), "+f"(c[2]), "+f"(c[3])
        : "r"(a[0]), "r"(a[1]), "r"(a[2]), "r"(a[3]), "r"(b[0]), "r"(b[1]));
}

__device__ __forceinline__ void ldm_x4(unsigned& r0, unsigned& r1, unsigned& r2, unsigned& r3,
                                       uint32_t addr) {
    asm volatile("ldmatrix.sync.aligned.m8n8.x4.shared.b16 {%0,%1,%2,%3}, [%4];"
                 : "=r"(r0), "=r"(r1), "=r"(r2), "=r"(r3) : "r"(addr));
}
__device__ __forceinline__ void ldm_x4_t(unsigned& r0, unsigned& r1, unsigned& r2, unsigned& r3,
                                         uint32_t addr) {
    asm volatile("ldmatrix.sync.aligned.m8n8.x4.trans.shared.b16 {%0,%1,%2,%3}, [%4];"
                 : "=r"(r0), "=r"(r1), "=r"(r2), "=r"(r3) : "r"(addr));
}

__device__ __forceinline__ void cp_async16(void* smem, const void* gmem) {
    unsigned saddr = (unsigned)__cvta_generic_to_shared(smem);
    asm volatile("cp.async.cg.shared.global [%0], [%1], 16;\n" :: "r"(saddr), "l"(gmem));
}
#define CP_COMMIT() asm volatile("cp.async.commit_group;\n" ::: "memory")
#define CP_WAIT1()  asm volatile("cp.async.wait_group 1;\n" ::: "memory")

// ---------------------------------------------------------------------------
// pre-pass kernels
// ---------------------------------------------------------------------------
__global__ void to_half_kernel(const float* __restrict__ in, unsigned* __restrict__ out, int n4)
{
    int i = blockIdx.x * blockDim.x + threadIdx.x;
    if (i < n4) {
        float4 v = ((const float4*)in)[i];
        uint2 o;
        o.x = pack_h2(v.x, v.y);
        o.y = pack_h2(v.z, v.w);
        ((uint2*)out)[i] = o;
    }
}

__global__ void transpose_h_kernel(const float* __restrict__ in, __half* __restrict__ out,
                                   int K, int N)
{
    __shared__ float tile[32][33];
    int k0 = blockIdx.y * 32, n0 = blockIdx.x * 32;
    int tx = threadIdx.x, ty = threadIdx.y;
    #pragma unroll
    for (int j = 0; j < 4; ++j)
        tile[ty + 8*j][tx] = in[(size_t)(k0 + ty + 8*j) * N + n0 + tx];
    __syncthreads();
    #pragma unroll
    for (int j = 0; j < 4; ++j)
        out[(size_t)(n0 + ty + 8*j) * K + k0 + tx] = __float2half_rn(tile[tx][ty + 8*j]);
}

// ---------------------------------------------------------------------------
// fp16 GEMM v2: BM=128, BN=128, BK=32, 256 threads, 2 CTAs/SM, ldmatrix frags.
// Warp tile 64x32 (8 warps, 2 along M x 4 along N).
// C[M,N] = A[M,K] @ Bt[N,K]^T + bias[N].
// ---------------------------------------------------------------------------
#define GBM 128
#define GBN 128
#define GBK 32
#define HNST 3
#define HPI 40                      // pitch (halves); 80B rows -> ldmatrix conflict-free
#define HAST (GBM * HPI)            // 5120 halves / stage
#define HBST (GBN * HPI)
#define GEMMH_SMEM ((HNST*(HAST + HBST)) * 2)   // 61440 B

template<int OUTF32>
__global__ __launch_bounds__(256, 2)
void gemm_h(const __half* __restrict__ A, const __half* __restrict__ Bt,
            const float* __restrict__ bias, void* __restrict__ Cout,
            int Mdim, int Ndim, int Kdim)
{
    extern __shared__ __half hsm[];
    __half* As = hsm;                       // [HNST][128][HPI]
    __half* Bs = hsm + HNST * HAST;         // [HNST][128][HPI]

    const int tid  = threadIdx.x;
    const int lane = tid & 31;
    const int wid  = tid >> 5;
    const int g    = lane >> 2;
    const int t    = lane & 3;
    const int warp_m = wid & 1;             // 2 warps along M (64 rows)
    const int warp_n = wid >> 1;            // 4 warps along N (32 cols)
    const int m0 = blockIdx.y * GBM;
    const int n0 = blockIdx.x * GBN;

    // cp.async mapping: rows r, r+64; unit au (4 x 16B per 64-half row)
    const int arow = tid >> 2, au = tid & 3;

    const __half* Ap = A  + (size_t)(m0 + arow) * Kdim + 8 * au;
    const __half* Bp = Bt + (size_t)(n0 + arow) * Kdim + 8 * au;

    __half* Asw = As + arow * HPI + 8 * au;
    __half* Bsw = Bs + arow * HPI + 8 * au;

    // ldmatrix per-lane offsets (byte)
    const int grp = lane >> 3, l7 = lane & 7;
    const uint32_t asm32 = (uint32_t)__cvta_generic_to_shared(As);
    const uint32_t bsm32 = (uint32_t)__cvta_generic_to_shared(Bs);
    // A m16xk16 tile: lanes 0-15 -> rows, lanes 16-31 -> +8 halves (k)
    const uint32_t aoff = ((uint32_t)(warp_m*64 + (lane & 15)) * HPI + (uint32_t)(lane >> 4) * 8) * 2;
    // B n16xk16 tile: grp0 rows0-7 k0-7, grp1 rows0-7 k8-15, grp2 rows8-15 k0-7, grp3 rows8-15 k8-15
    const uint32_t boff = ((uint32_t)(warp_n*32 + (grp >> 1)*8 + l7) * HPI) * 2 + (uint32_t)(grp & 1) * 16;

    float c[4][4][4];
    #pragma unroll
    for (int mi = 0; mi < 4; ++mi)
        #pragma unroll
        for (int ni = 0; ni < 4; ++ni)
            #pragma unroll
            for (int j = 0; j < 4; ++j) c[mi][ni][j] = 0.f;

    const int ntiles = Kdim / GBK;

    // prologue: fill stages 0,1
    #pragma unroll
    for (int st = 0; st < 2; ++st) {
        cp_async16(Asw + st*HAST,           Ap + st*GBK);
        cp_async16(Asw + st*HAST + 64*HPI,  Ap + (size_t)64*Kdim + st*GBK);
        cp_async16(Bsw + st*HBST,           Bp + st*GBK);
        cp_async16(Bsw + st*HBST + 64*HPI,  Bp + (size_t)64*Kdim + st*GBK);
        CP_COMMIT();
    }

    int stage = 0;
    for (int i = 0; i < ntiles; ++i) {
        CP_WAIT1();
        __syncthreads();

        const uint32_t abase = asm32 + (uint32_t)stage * (HAST * 2);
        const uint32_t bbase = bsm32 + (uint32_t)stage * (HBST * 2);

        #pragma unroll
        for (int kk = 0; kk < 2; ++kk) {
            unsigned afr[4][4], bfr[4][2];
            #pragma unroll
            for (int mi = 0; mi < 4; ++mi)
                ldm_x4(afr[mi][0], afr[mi][1], afr[mi][2], afr[mi][3],
                       abase + aoff + (uint32_t)mi * (16*HPI*2) + kk*32);
            #pragma unroll
            for (int nj = 0; nj < 2; ++nj) {
                unsigned r0, r1, r2, r3;
                ldm_x4(r0, r1, r2, r3,
                       bbase + boff + (uint32_t)nj * (16*HPI*2) + kk*32);
                bfr[2*nj][0] = r0;   bfr[2*nj][1] = r1;
                bfr[2*nj+1][0] = r2; bfr[2*nj+1][1] = r3;
            }
            #pragma unroll
            for (int mi = 0; mi < 4; ++mi)
                #pragma unroll
                for (int ni = 0; ni < 4; ++ni)
                    mma_h(c[mi][ni], afr[mi], bfr[ni]);
        }

        __syncthreads();

        int nx = i + 2;
        if (nx < ntiles) {
            int ns = nx % HNST;
            cp_async16(Asw + ns*HAST,          Ap + nx*GBK);
            cp_async16(Asw + ns*HAST + 64*HPI, Ap + (size_t)64*Kdim + nx*GBK);
            cp_async16(Bsw + ns*HBST,          Bp + nx*GBK);
            cp_async16(Bsw + ns*HBST + 64*HPI, Bp + (size_t)64*Kdim + nx*GBK);
        }
        CP_COMMIT();
        stage = (stage + 1 == HNST) ? 0 : stage + 1;
    }

    // epilogue
    #pragma unroll
    for (int mi = 0; mi < 4; ++mi) {
        #pragma unroll
        for (int ni = 0; ni < 4; ++ni) {
            int row = m0 + warp_m*64 + mi*16 + g;
            int col = n0 + warp_n*32 + ni*8 + 2*t;
            float2 bb = *(const float2*)(bias + col);
            float v00 = c[mi][ni][0] + bb.x, v01 = c[mi][ni][1] + bb.y;
            float v10 = c[mi][ni][2] + bb.x, v11 = c[mi][ni][3] + bb.y;
            if (OUTF32) {
                float* Cf = (float*)Cout;
                float2 o0 = {v00, v01}, o1 = {v10, v11};
                *(float2*)(Cf + (size_t)row * Ndim + col) = o0;
                *(float2*)(Cf + (size_t)(row + 8) * Ndim + col) = o1;
            } else {
                __half* Ch = (__half*)Cout;
                *(unsigned*)(Ch + (size_t)row * Ndim + col) = pack_h2(v00, v01);
                *(unsigned*)(Ch + (size_t)(row + 8) * Ndim + col) = pack_h2(v10, v11);
            }
        }
    }
}

// ---------------------------------------------------------------------------
// fp16 flash attention v2 (unchanged from R11).
// ---------------------------------------------------------------------------
#define QTILE 128
#define KTILE 64
#define HP 72
#define NEG_BIG (-1e30f)
#define KVSTR (KTILE*HP*2)
#define ATTN_SMEM ((QTILE*HP + 2*KTILE*HP + 2*KTILE*HP) * 2)   // 55296 B

__global__ __launch_bounds__(256)
void attn_h2_kernel(const __half* __restrict__ qkv, __half* __restrict__ Y)
{
    extern __shared__ __half smh[];
    __half* Qs  = smh;
    __half* Kst = Qs + QTILE * HP;
    __half* Vst = Kst + 2 * KTILE * HP;

    const int bh = blockIdx.y;
    const int b  = bh >> 4;
    const int h  = bh & 15;
    const int q0 = blockIdx.x * QTILE;

    const int tid  = threadIdx.x;
    const int lane = tid & 31;
    const int wid  = tid >> 5;
    const int g    = lane >> 2;
    const int t    = lane & 3;
    const int wr   = wid * 16;

    const uint32_t qb32 = (uint32_t)__cvta_generic_to_shared(Qs);
    const uint32_t kb32 = (uint32_t)__cvta_generic_to_shared(Kst);
    const uint32_t vb32 = (uint32_t)__cvta_generic_to_shared(Vst);

    const int grp = lane >> 3, l7 = lane & 7;
    const uint32_t qoff = ((uint32_t)(wr + (lane & 15)) * HP + (uint32_t)(lane >> 4) * 8) * 2;
    const uint32_t koff = ((uint32_t)((grp >> 1) * 8 + l7) * HP) * 2 + (uint32_t)(grp & 1) * 16;
    const uint32_t voff = ((uint32_t)((grp & 1) * 8 + l7) * HP) * 2 + (uint32_t)(grp >> 1) * 16;

    const size_t tok_base = (size_t)b * TT * N_QKV;
    const float scale = 0.03125f;

    const int q_hi  = q0 + wr + 15;
    const int ktmax = (q0 + QTILE - 1) / KTILE;

    #pragma unroll
    for (int it = 0; it < 4; ++it) {
        int idx = tid + it * 256;
        int r = idx >> 3, q8 = idx & 7;
        cp_async16(Qs + r * HP + 8*q8,
                   qkv + tok_base + (size_t)(q0 + r) * N_QKV + h*DD + 8*q8);
    }
    #pragma unroll
    for (int it = 0; it < 2; ++it) {
        int idx = tid + it * 256;
        int r = idx >> 3, q8 = idx & 7;
        size_t rowb = tok_base + (size_t)r * N_QKV + h*DD + 8*q8;
        cp_async16(Kst + r * HP + 8*q8, qkv + rowb + CC);
        cp_async16(Vst + r * HP + 8*q8, qkv + rowb + 2*CC);
    }
    CP_COMMIT();
    if (ktmax >= 1) {
        #pragma unroll
        for (int it = 0; it < 2; ++it) {
            int idx = tid + it * 256;
            int r = idx >> 3, q8 = idx & 7;
            size_t rowb = tok_base + (size_t)(KTILE + r) * N_QKV + h*DD + 8*q8;
            cp_async16(Kst + KTILE*HP + r * HP + 8*q8, qkv + rowb + CC);
            cp_async16(Vst + KTILE*HP + r * HP + 8*q8, qkv + rowb + 2*CC);
        }
    }
    CP_COMMIT();
    CP_WAIT1();
    __syncthreads();

    unsigned qa[4][4];
    #pragma unroll
    for (int kk = 0; kk < 4; ++kk)
        ldm_x4(qa[kk][0], qa[kk][1], qa[kk][2], qa[kk][3], qb32 + qoff + kk*32);

    float o[8][4];
    #pragma unroll
    for (int n = 0; n < 8; ++n)
        #pragma unroll
        for (int j = 0; j < 4; ++j) o[n][j] = 0.f;
    float mrow[2] = {NEG_BIG, NEG_BIG};
    float lrow[2] = {0.f, 0.f};

    for (int kt = 0; kt <= ktmax; ++kt) {
        const int k0 = kt * KTILE;
        const uint32_t kbase = kb32 + (uint32_t)(kt & 1) * KVSTR;
        const uint32_t vbase = vb32 + (uint32_t)(kt & 1) * KVSTR;

        if (k0 <= q_hi) {
            float s[8][4];
            #pragma unroll
            for (int n = 0; n < 8; ++n)
                #pragma unroll
                for (int j = 0; j < 4; ++j) s[n][j] = 0.f;

            #pragma unroll
            for (int kk = 0; kk < 4; ++kk) {
                #pragma unroll
                for (int p = 0; p < 4; ++p) {
                    unsigned r0, r1, r2, r3;
                    ldm_x4(r0, r1, r2, r3, kbase + koff + (uint32_t)p * (16*HP*2) + kk*32);
                    unsigned b0[2] = {r0, r1}, b1[2] = {r2, r3};
                    mma_h(s[2*p],     qa[kk], b0);
                    mma_h(s[2*p + 1], qa[kk], b1);
                }
            }

            #pragma unroll
            for (int n = 0; n < 8; ++n)
                #pragma unroll
                for (int j = 0; j < 4; ++j) s[n][j] *= scale;

            if (k0 + KTILE - 1 > q0 + wr) {
                int r0q = q0 + wr + g, r1q = r0q + 8;
                #pragma unroll
                for (int n = 0; n < 8; ++n) {
                    int key = k0 + n*8 + 2*t;
                    if (key     > r0q) s[n][0] = NEG_BIG;
                    if (key + 1 > r0q) s[n][1] = NEG_BIG;
                    if (key     > r1q) s[n][2] = NEG_BIG;
                    if (key + 1 > r1q) s[n][3] = NEG_BIG;
                }
            }

            #pragma unroll
            for (int half = 0; half < 2; ++half) {
                float rm = NEG_BIG;
                #pragma unroll
                for (int n = 0; n < 8; ++n)
                    rm = fmaxf(rm, fmaxf(s[n][2*half], s[n][2*half+1]));
                rm = fmaxf(rm, __shfl_xor_sync(0xffffffffu, rm, 1));
                rm = fmaxf(rm, __shfl_xor_sync(0xffffffffu, rm, 2));
                float mn = fmaxf(mrow[half], rm);
                float alpha = __expf(mrow[half] - mn);
                float ps = 0.f;
                #pragma unroll
                for (int n = 0; n < 8; ++n) {
                    float p0 = __expf(s[n][2*half]   - mn);
                    float p1 = __expf(s[n][2*half+1] - mn);
                    s[n][2*half] = p0; s[n][2*half+1] = p1;
                    ps += p0 + p1;
                }
                ps += __shfl_xor_sync(0xffffffffu, ps, 1);
                ps += __shfl_xor_sync(0xffffffffu, ps, 2);
                lrow[half] = lrow[half] * alpha + ps;
                mrow[half] = mn;
                #pragma unroll
                for (int n = 0; n < 8; ++n) {
                    o[n][2*half]   *= alpha;
                    o[n][2*half+1] *= alpha;
                }
            }

            #pragma unroll
            for (int kk = 0; kk < 4; ++kk) {
                unsigned pa[4];
                pa[0] = pack_h2(s[2*kk][0],     s[2*kk][1]);
                pa[1] = pack_h2(s[2*kk][2],     s[2*kk][3]);
                pa[2] = pack_h2(s[2*kk + 1][0], s[2*kk + 1][1]);
                pa[3] = pack_h2(s[2*kk + 1][2], s[2*kk + 1][3]);
                #pragma unroll
                for (int p = 0; p < 4; ++p) {
                    unsigned r0, r1, r2, r3;
                    ldm_x4_t(r0, r1, r2, r3, vbase + voff + (uint32_t)kk * (16*HP*2) + p*32);
                    unsigned b0[2] = {r0, r1}, b1[2] = {r2, r3};
                    mma_h(o[2*p],     pa, b0);
                    mma_h(o[2*p + 1], pa, b1);
                }
            }
        }

        __syncthreads();

        if (kt + 2 <= ktmax) {
            int k0n = (kt + 2) * KTILE;
            int st = kt & 1;
            #pragma unroll
            for (int it = 0; it < 2; ++it) {
                int idx = tid + it * 256;
                int r = idx >> 3, q8 = idx & 7;
                size_t rowb = tok_base + (size_t)(k0n + r) * N_QKV + h*DD + 8*q8;
                cp_async16(Kst + st*KTILE*HP + r * HP + 8*q8, qkv + rowb + CC);
                cp_async16(Vst + st*KTILE*HP + r * HP + 8*q8, qkv + rowb + 2*CC);
            }
        }
        CP_COMMIT();
        CP_WAIT1();
        __syncthreads();
    }

    #pragma unroll
    for (int half = 0; half < 2; ++half) {
        float inv = 1.0f / lrow[half];
        int row = q0 + wr + g + half * 8;
        __half* yb = Y + (size_t)(b * TT + row) * CC + h*DD + 2*t;
        #pragma unroll
        for (int n = 0; n < 8; ++n)
            *(unsigned*)(yb + n*8) = pack_h2(o[n][2*half] * inv, o[n][2*half+1] * inv);
    }
}

// ---------------------------------------------------------------------------
// Launch
// ---------------------------------------------------------------------------
extern "C" void kernel_launch(void* const* d_in, const int* in_sizes, int n_in,
                              void* d_out, int out_size)
{
    const float* x      = (const float*)d_in[0];
    const float* W_attn = (const float*)d_in[1];
    const float* b_attn = (const float*)d_in[2];
    const float* W_proj = (const float*)d_in[3];
    const float* b_proj = (const float*)d_in[4];
    float* out = (float*)d_out;

    __half *qkv_ptr, *y_ptr, *xh_ptr, *wa_ptr, *wp_ptr;
    cudaGetSymbolAddress((void**)&qkv_ptr, g_qkv);
    cudaGetSymbolAddress((void**)&y_ptr, g_y);
    cudaGetSymbolAddress((void**)&xh_ptr, g_xh);
    cudaGetSymbolAddress((void**)&wa_ptr, g_wa);
    cudaGetSymbolAddress((void**)&wp_ptr, g_wp);

    cudaFuncSetAttribute(attn_h2_kernel, cudaFuncAttributeMaxDynamicSharedMemorySize, ATTN_SMEM);
    cudaFuncSetAttribute(gemm_h<0>, cudaFuncAttributeMaxDynamicSharedMemorySize, GEMMH_SMEM);
    cudaFuncSetAttribute(gemm_h<1>, cudaFuncAttributeMaxDynamicSharedMemorySize, GEMMH_SMEM);

    // 0) pre-pass
    {
        int n4 = M_TOK * CC / 4;
        to_half_kernel<<<(n4 + 255)/256, 256>>>(x, (unsigned*)xh_ptr, n4);
        transpose_h_kernel<<<dim3(N_QKV/32, CC/32), dim3(32, 8)>>>(W_attn, wa_ptr, CC, N_QKV);
        transpose_h_kernel<<<dim3(CC/32, CC/32), dim3(32, 8)>>>(W_proj, wp_ptr, CC, CC);
    }

    // 1) qkv = x @ W_attn + b_attn   (fp16 out)
    gemm_h<0><<<dim3(N_QKV/GBN, M_TOK/GBM), 256, GEMMH_SMEM>>>(
        xh_ptr, wa_ptr, b_attn, qkv_ptr, M_TOK, N_QKV, CC);

    // 2) flash attention v2
    attn_h2_kernel<<<dim3(TT/QTILE, BB*HH), 256, ATTN_SMEM>>>(qkv_ptr, y_ptr);

    // 3) out = y @ W_proj + b_proj   (fp32 out)
    gemm_h<1><<<dim3(CC/GBN, M_TOK/GBM), 256, GEMMH_SMEM>>>(
        y_ptr, wp_ptr, b_proj, out, M_TOK, CC, CC);
}